// round 8
// baseline (speedup 1.0000x reference)
#include <cuda_runtime.h>
#include <cuda_bf16.h>
#include <math_constants.h>

#define DIM     2048
#define NHEADS  16
#define HD      128
#define BATCH   2
#define SEQ     4096
#define QKV_COLS (3*DIM)        // 6144
#define MROWS   (BATCH*SEQ)     // 8192

// ---------------------------------------------------------------------------
// Device-global scratch
// ---------------------------------------------------------------------------
__device__ float g_Q[(size_t)BATCH*NHEADS*SEQ*HD];   // pre-norm Q (fp32)
__device__ float g_K[(size_t)BATCH*NHEADS*SEQ*HD];   // pre-norm K (fp32)
__device__ __nv_bfloat16 g_Qh[(size_t)BATCH*NHEADS*SEQ*HD];
__device__ __nv_bfloat16 g_Ql[(size_t)BATCH*NHEADS*SEQ*HD];
__device__ __nv_bfloat16 g_Kh[(size_t)BATCH*NHEADS*SEQ*HD];
__device__ __nv_bfloat16 g_Kl[(size_t)BATCH*NHEADS*SEQ*HD];
__device__ __nv_bfloat16 g_Vh[(size_t)BATCH*NHEADS*SEQ*HD];
__device__ __nv_bfloat16 g_Vl[(size_t)BATCH*NHEADS*SEQ*HD];
__device__ __nv_bfloat16 g_xh[(size_t)MROWS*DIM];
__device__ __nv_bfloat16 g_xl[(size_t)MROWS*DIM];
__device__ __nv_bfloat16 g_wth[(size_t)QKV_COLS*DIM];  // W^T [n][k]
__device__ __nv_bfloat16 g_wtl[(size_t)QKV_COLS*DIM];

// ---------------------------------------------------------------------------
// PTX helpers (arch-neutral: mma.sync / ldmatrix / cp.async, sm_80+)
// ---------------------------------------------------------------------------
__device__ __forceinline__ unsigned smem_u32(const void* p) {
    unsigned a;
    asm("{ .reg .u64 t; cvta.to.shared.u64 t, %1; cvt.u32.u64 %0, t; }"
        : "=r"(a) : "l"(p));
    return a;
}
__device__ __forceinline__ void ldsm_x4(unsigned r[4], unsigned a) {
    asm volatile("ldmatrix.sync.aligned.m8n8.x4.shared.b16 {%0,%1,%2,%3}, [%4];"
                 : "=r"(r[0]), "=r"(r[1]), "=r"(r[2]), "=r"(r[3]) : "r"(a));
}
__device__ __forceinline__ void ldsm_x4_t(unsigned r[4], unsigned a) {
    asm volatile("ldmatrix.sync.aligned.m8n8.x4.trans.shared.b16 {%0,%1,%2,%3}, [%4];"
                 : "=r"(r[0]), "=r"(r[1]), "=r"(r[2]), "=r"(r[3]) : "r"(a));
}
__device__ __forceinline__ void mma16816(float c[4], const unsigned a[4],
                                         const unsigned b[2]) {
    asm volatile(
        "mma.sync.aligned.m16n8k16.row.col.f32.bf16.bf16.f32 "
        "{%0,%1,%2,%3}, {%4,%5,%6,%7}, {%8,%9}, {%0,%1,%2,%3};"
        : "+f"(c[0]), "+f"(c[1]), "+f"(c[2]), "+f"(c[3])
        : "r"(a[0]), "r"(a[1]), "r"(a[2]), "r"(a[3]), "r"(b[0]), "r"(b[1]));
}
__device__ __forceinline__ unsigned pack_bf16(float lo, float hi) {
    unsigned r;
    asm("cvt.rn.bf16x2.f32 %0, %1, %2;" : "=r"(r) : "f"(hi), "f"(lo));
    return r;
}
__device__ __forceinline__ float bf16_rn(float x) {
    return __bfloat162float(__float2bfloat16(x));
}
__device__ __forceinline__ float ex2(float x) {
    float y;
    asm("ex2.approx.f32 %0, %1;" : "=f"(y) : "f"(x));
    return y;
}
__device__ __forceinline__ void cp16(unsigned dst, const void* src) {
    asm volatile("cp.async.cg.shared.global [%0], [%1], 16;"
                 :: "r"(dst), "l"(src));
}
#define CP_COMMIT()  asm volatile("cp.async.commit_group;" ::: "memory")
#define CP_WAIT(n)   asm volatile("cp.async.wait_group %0;" :: "n"(n) : "memory")

// ---------------------------------------------------------------------------
// Kernel 0a: split x (fp32) into bf16 hi/lo
// ---------------------------------------------------------------------------
__global__ void convert_x_kernel(const float* __restrict__ x)
{
    size_t i = ((size_t)blockIdx.x * 256 + threadIdx.x) * 4;
    float4 v = *(const float4*)(x + i);
    float f[4] = {v.x, v.y, v.z, v.w};
    __nv_bfloat16 h[4], lo[4];
#pragma unroll
    for (int j = 0; j < 4; j++) {
        h[j] = __float2bfloat16(f[j]);
        lo[j] = __float2bfloat16(f[j] - __bfloat162float(h[j]));
    }
    *(uint2*)(g_xh + i) = *(uint2*)h;
    *(uint2*)(g_xl + i) = *(uint2*)lo;
}

// ---------------------------------------------------------------------------
// Kernel 0b: transpose W [k][n] -> [n][k], split into bf16 hi/lo
// ---------------------------------------------------------------------------
__global__ void convert_w_kernel(const float* __restrict__ W)
{
    __shared__ float tile[32][33];
    int tx = threadIdx.x, ty = threadIdx.y;          // block (32, 8)
    int n0 = blockIdx.x * 32, k0 = blockIdx.y * 32;
#pragma unroll
    for (int r = 0; r < 4; r++) {
        int k = k0 + ty + r * 8;
        tile[ty + r * 8][tx] = W[(size_t)k * QKV_COLS + n0 + tx];
    }
    __syncthreads();
#pragma unroll
    for (int r = 0; r < 4; r++) {
        int n = n0 + ty + r * 8;
        int k = k0 + tx;
        float v = tile[tx][ty + r * 8];
        __nv_bfloat16 h = __float2bfloat16(v);
        g_wth[(size_t)n * DIM + k] = h;
        g_wtl[(size_t)n * DIM + k] = __float2bfloat16(v - __bfloat162float(h));
    }
}

// ---------------------------------------------------------------------------
// Kernel 1: QKV GEMM via mma.sync bf16 x3, CTA 128x256, K-chunk 64,
// 2-stage cp.async pipeline (221 KB smem). 8 warps, warp tile 32x128.
// ---------------------------------------------------------------------------
#define G_STR    144                // smem row stride bytes (64 bf16 + 16B pad)
#define G_A_ARR  (128*G_STR)        // 18432
#define G_B_ARR  (256*G_STR)        // 36864
#define G_STAGE  (2*G_A_ARR + 2*G_B_ARR)   // 110592
#define GEMM_SMEM (2*G_STAGE)       // 221184

__global__ __launch_bounds__(256, 1) void qkv_gemm_mma_kernel(
    const float* __restrict__ bias)
{
    extern __shared__ char smem[];
    const unsigned sbase = smem_u32(smem);
    const int tid = threadIdx.x;
    const int wid = tid >> 5, lane = tid & 31;
    const int warp_m = wid >> 1, warp_n = wid & 1;
    const int gM0 = blockIdx.y << 7;
    const int gN0 = blockIdx.x << 8;
    const int l15 = lane & 15;

    float acc[2][16][4];
#pragma unroll
    for (int i = 0; i < 2; i++)
#pragma unroll
        for (int j = 0; j < 16; j++)
#pragma unroll
            for (int e = 0; e < 4; e++) acc[i][j][e] = 0.f;

    auto stage_load = [&](int st, int it) {
        unsigned sb = sbase + st * G_STAGE;
        int k0 = it * 64;
#pragma unroll
        for (int l = 0; l < 24; l++) {
            int t = tid + (l << 8);                // 0..6143
            if (t < 2048) {                        // A: Ah, Al
                int arr = t >> 10, w = t & 1023;
                int row = w >> 3, c4 = w & 7;
                const uint4* s = arr ? (const uint4*)g_xl : (const uint4*)g_xh;
                size_t gi = (((size_t)(gM0 + row) * DIM + k0) >> 3) + c4;
                cp16(sb + arr * G_A_ARR + row * G_STR + c4 * 16, s + gi);
            } else {                               // B: Bh, Bl
                int t2 = t - 2048;
                int arr = t2 >> 11, w = t2 & 2047;
                int row = w >> 3, c4 = w & 7;
                const uint4* s = arr ? (const uint4*)g_wtl : (const uint4*)g_wth;
                size_t gi = (((size_t)(gN0 + row) * DIM + k0) >> 3) + c4;
                cp16(sb + 2 * G_A_ARR + arr * G_B_ARR + row * G_STR + c4 * 16,
                     s + gi);
            }
        }
    };

    const int NIT = DIM / 64;        // 32
    stage_load(0, 0); CP_COMMIT();
    stage_load(1, 1); CP_COMMIT();

    for (int it = 0; it < NIT; ++it) {
        CP_WAIT(1);
        __syncthreads();

        unsigned sb = sbase + (it & 1) * G_STAGE;
        unsigned sAh = sb, sAl = sb + G_A_ARR;
        unsigned sBh = sb + 2 * G_A_ARR, sBl = sb + 2 * G_A_ARR + G_B_ARR;

#pragma unroll
        for (int ks = 0; ks < 4; ks++) {
            unsigned ah[2][4], al[2][4];
            int acol = ks * 16 + (lane >> 4) * 8;
#pragma unroll
            for (int i = 0; i < 2; i++) {
                int arow = warp_m * 32 + i * 16 + l15;
                ldsm_x4(ah[i], sAh + arow * G_STR + acol * 2);
                ldsm_x4(al[i], sAl + arow * G_STR + acol * 2);
            }
            int brow_off = (lane >> 4) * 8 + (lane & 7);
            int bcol = ks * 16 + ((lane >> 3) & 1) * 8;
#pragma unroll
            for (int jj = 0; jj < 8; jj++) {
                unsigned bh4[4], bl4[4];
                unsigned boff = (warp_n * 128 + jj * 16 + brow_off) * G_STR
                                + bcol * 2;
                ldsm_x4(bh4, sBh + boff);
                ldsm_x4(bl4, sBl + boff);
                mma16816(acc[0][2*jj],   ah[0], bh4);
                mma16816(acc[0][2*jj+1], ah[0], bh4 + 2);
                mma16816(acc[1][2*jj],   ah[1], bh4);
                mma16816(acc[1][2*jj+1], ah[1], bh4 + 2);
                mma16816(acc[0][2*jj],   ah[0], bl4);
                mma16816(acc[0][2*jj+1], ah[0], bl4 + 2);
                mma16816(acc[1][2*jj],   ah[1], bl4);
                mma16816(acc[1][2*jj+1], ah[1], bl4 + 2);
                mma16816(acc[0][2*jj],   al[0], bh4);
                mma16816(acc[0][2*jj+1], al[0], bh4 + 2);
                mma16816(acc[1][2*jj],   al[1], bh4);
                mma16816(acc[1][2*jj+1], al[1], bh4 + 2);
            }
        }
        __syncthreads();                     // all warps done reading stage
        if (it + 2 < NIT) stage_load(it & 1, it + 2);
        CP_COMMIT();                         // unconditional: keeps count in sync
    }

    // Epilogue: bias + de-interleave scatter
    const int gr = lane >> 2, qc = (lane & 3) * 2;
#pragma unroll
    for (int i = 0; i < 2; i++) {
        int rbase = gM0 + warp_m * 32 + i * 16 + gr;
#pragma unroll
        for (int half = 0; half < 2; half++) {
            int row = rbase + half * 8;
            int b = row >> 12;
            int n = row & (SEQ - 1);
#pragma unroll
            for (int j = 0; j < 16; j++) {
                int cb = gN0 + warp_n * 128 + j * 8 + qc;
#pragma unroll
                for (int e = 0; e < 2; e++) {
                    int col = cb + e;
                    float v = acc[i][j][half * 2 + e] + __ldg(bias + col);
                    int h = col / 384;
                    int rem = col - h * 384;
                    int d = rem / 3;
                    int jj = rem - 3 * d;
                    size_t off = ((size_t)(b * NHEADS + h) * SEQ + n) * HD + d;
                    if (jj == 0)      g_Q[off] = v;
                    else if (jj == 1) g_K[off] = v;
                    else {
                        __nv_bfloat16 vh = __float2bfloat16(v);
                        g_Vh[off] = vh;
                        g_Vl[off] = __float2bfloat16(v - __bfloat162float(vh));
                    }
                }
            }
        }
    }
}

// ---------------------------------------------------------------------------
// Kernel 2: RMSNorm + RoPE, warp-per-row (float4 loads, shuffle-only reduce,
// RoPE pairs in-thread). Q pre-scaled by (1/sqrt(HD))*log2(e).
// ---------------------------------------------------------------------------
__global__ __launch_bounds__(256) void norm_rope_kernel(
    const float* __restrict__ rot, const float* __restrict__ qw,
    const float* __restrict__ kw)
{
    const int lane = threadIdx.x & 31;
    const int row = blockIdx.x * 8 + (threadIdx.x >> 5);
    const int n = row & (SEQ - 1);
    const size_t base = (size_t)row * HD + lane * 4;

    float4 q = *(const float4*)(g_Q + base);
    float4 k = *(const float4*)(g_K + base);

    float q2 = q.x*q.x + q.y*q.y + q.z*q.z + q.w*q.w;
    float k2 = k.x*k.x + k.y*k.y + k.z*k.z + k.w*k.w;
#pragma unroll
    for (int off = 16; off; off >>= 1) {
        q2 += __shfl_xor_sync(0xffffffffu, q2, off);
        k2 += __shfl_xor_sync(0xffffffffu, k2, off);
    }
    float qs = rsqrtf(q2 * (1.0f / HD) + 1e-6f);
    float ks = rsqrtf(k2 * (1.0f / HD) + 1e-6f);

    float4 qwv = *(const float4*)(qw + lane * 4);
    float4 kwv = *(const float4*)(kw + lane * 4);

    float qn0 = q.x * qs * qwv.x, qn1 = q.y * qs * qwv.y;
    float qn2 = q.z * qs * qwv.z, qn3 = q.w * qs * qwv.w;
    float kn0 = k.x * ks * kwv.x, kn1 = k.y * ks * kwv.y;
    float kn2 = k.z * ks * kwv.z, kn3 = k.w * ks * kwv.w;

    const float* rp = rot + (size_t)n * 256 + lane * 8;
    float4 rA = *(const float4*)rp;
    float4 rB = *(const float4*)(rp + 4);

    const float scale = 0.08838834764831845f * 1.4426950408889634f;
    float qo0 = (rA.x * qn0 + rA.y * qn1) * scale;
    float qo1 = (rA.z * qn0 + rA.w * qn1) * scale;
    float qo2 = (rB.x * qn2 + rB.y * qn3) * scale;
    float qo3 = (rB.z * qn2 + rB.w * qn3) * scale;
    float ko0 = rA.x * kn0 + rA.y * kn1;
    float ko1 = rA.z * kn0 + rA.w * kn1;
    float ko2 = rB.x * kn2 + rB.y * kn3;
    float ko3 = rB.z * kn2 + rB.w * kn3;

    uint2 qh = make_uint2(pack_bf16(qo0, qo1), pack_bf16(qo2, qo3));
    uint2 kh = make_uint2(pack_bf16(ko0, ko1), pack_bf16(ko2, ko3));
    uint2 ql = make_uint2(
        pack_bf16(qo0 - bf16_rn(qo0), qo1 - bf16_rn(qo1)),
        pack_bf16(qo2 - bf16_rn(qo2), qo3 - bf16_rn(qo3)));
    uint2 kl = make_uint2(
        pack_bf16(ko0 - bf16_rn(ko0), ko1 - bf16_rn(ko1)),
        pack_bf16(ko2 - bf16_rn(ko2), ko3 - bf16_rn(ko3)));

    *(uint2*)(g_Qh + base) = qh;
    *(uint2*)(g_Ql + base) = ql;
    *(uint2*)(g_Kh + base) = kh;
    *(uint2*)(g_Kl + base) = kl;
}

// ---------------------------------------------------------------------------
// Kernel 3: Flash attention, BM=64 (4 warps), BN=32, D=128, 128 threads.
// smem = 3 stages x 34816 B = 104448 -> TWO CTAs per SM. The co-resident
// CTA covers barrier/LDSM bubbles (independent barriers + cp.async queues).
// Q fragments register-resident; no-max exp2 softmax; deferred l reduction.
// ---------------------------------------------------------------------------
#define A_STR    272                 // smem row stride bytes (128 bf16 + pad)
#define A_ARR    (32*A_STR)          // 8704  (32-row array)
#define A_QARR   (64*A_STR)          // 17408 (64-row Q array)
#define A_STAGE  (4*A_ARR)           // Kh,Kl,Vh,Vl = 34816
#define ATT_SMEM (3*A_STAGE)         // 104448  -> 2 CTAs/SM

__global__ __launch_bounds__(128, 2) void attn_mma_kernel(float* __restrict__ out)
{
    extern __shared__ char smem[];
    const unsigned sbase = smem_u32(smem);
    const int bh = blockIdx.y;
    const int q0 = blockIdx.x << 6;          // 64 rows per CTA
    const int tid = threadIdx.x;
    const int wid = tid >> 5, lane = tid & 31;
    const int l15 = lane & 15;
    const int gr = lane >> 2, qc = (lane & 3) * 2;

    // --- Load Q tile (64 rows, hi/lo) into stage-0/1 region ---
    {
        const uint4* Qh4 = (const uint4*)g_Qh;
        const uint4* Ql4 = (const uint4*)g_Ql;
#pragma unroll
        for (int l = 0; l < 16; l++) {
            int t = tid + (l << 7);            // 0..2047
            int arr = t >> 10;                 // 0: hi, 1: lo (1024 chunks ea)
            int w = t & 1023;
            int row = w >> 4, c = w & 15;
            size_t gi = (((size_t)bh * SEQ + q0 + row) * HD >> 3) + c;
            const uint4* s = arr ? Ql4 : Qh4;
            cp16(sbase + arr * A_QARR + row * A_STR + c * 16, s + gi);
        }
    }
    CP_COMMIT();
    CP_WAIT(0);
    __syncthreads();

    // --- Hoist Q fragments to registers (once) ---
    unsigned qfh[8][4], qfl[8][4];
    {
        int arow = wid * 16 + l15;
#pragma unroll
        for (int ks = 0; ks < 8; ks++) {
            int acol = ks * 16 + (lane >> 4) * 8;
            ldsm_x4(qfh[ks], sbase + arow * A_STR + acol * 2);
            ldsm_x4(qfl[ks], sbase + A_QARR + arow * A_STR + acol * 2);
        }
    }
    __syncthreads();   // staging free before K/V pipeline reuses it

    const uint4* Kh4 = (const uint4*)g_Kh;
    const uint4* Kl4 = (const uint4*)g_Kl;
    const uint4* Vh4 = (const uint4*)g_Vh;
    const uint4* Vl4 = (const uint4*)g_Vl;

    auto stage_load = [&](int st, int kt) {
        unsigned sb = sbase + st * A_STAGE;
#pragma unroll
        for (int l = 0; l < 16; l++) {
            int t = tid + (l << 7);            // 0..2047
            int arr = t >> 9;                  // 0..3: Kh,Kl,Vh,Vl (512 ea)
            int w = t & 511;
            int row = w >> 4, c = w & 15;
            size_t gi = (((size_t)bh * SEQ + kt * 32 + row) * HD >> 3) + c;
            const uint4* s = (arr == 0) ? Kh4 : (arr == 1) ? Kl4
                             : (arr == 2) ? Vh4 : Vl4;
            cp16(sb + arr * A_ARR + row * A_STR + c * 16, s + gi);
        }
    };

    float O[16][4];
#pragma unroll
    for (int n = 0; n < 16; n++)
#pragma unroll
        for (int e = 0; e < 4; e++) O[n][e] = 0.f;
    float l0 = 0.f, l1 = 0.f;

    const int NKT = SEQ / 32;   // 128 iterations of 32 keys
    stage_load(0, 0); CP_COMMIT();
    stage_load(1, 1); CP_COMMIT();

    int buf = 0;
    for (int kt = 0; kt < NKT; kt++) {
        CP_WAIT(1);
        __syncthreads();        // stage kt visible; all warps done with kt-1

        // Early prefetch into the buffer freed by the barrier above.
        {
            int nb = buf + 2; if (nb >= 3) nb -= 3;
            if (kt + 2 < NKT) stage_load(nb, kt + 2);
            CP_COMMIT();
        }

        unsigned sb = sbase + buf * A_STAGE;
        unsigned sKh = sb, sKl = sb + A_ARR;
        unsigned sVh = sb + 2 * A_ARR, sVl = sb + 3 * A_ARR;

        // --- S = Q K^T (3-term), 32 keys ---
        float S[4][4];
#pragma unroll
        for (int j = 0; j < 4; j++)
#pragma unroll
            for (int e = 0; e < 4; e++) S[j][e] = 0.f;

        {
            int brow_off = (lane >> 4) * 8 + (lane & 7);
            int g_kh = ((lane >> 3) & 1) * 8;
#pragma unroll
            for (int ks = 0; ks < 8; ks++) {
                int bcol = ks * 16 + g_kh;
                unsigned kh4[2][4], kl4[2][4];
#pragma unroll
                for (int jj = 0; jj < 2; jj++) {
                    unsigned boff = (jj * 16 + brow_off) * A_STR + bcol * 2;
                    ldsm_x4(kh4[jj], sKh + boff);
                    ldsm_x4(kl4[jj], sKl + boff);
                }
#pragma unroll
                for (int jj = 0; jj < 2; jj++) {
                    mma16816(S[2*jj],   qfh[ks], kh4[jj]);
                    mma16816(S[2*jj+1], qfh[ks], kh4[jj] + 2);
                }
#pragma unroll
                for (int jj = 0; jj < 2; jj++) {
                    mma16816(S[2*jj],   qfh[ks], kl4[jj]);
                    mma16816(S[2*jj+1], qfh[ks], kl4[jj] + 2);
                }
#pragma unroll
                for (int jj = 0; jj < 2; jj++) {
                    mma16816(S[2*jj],   qfl[ks], kh4[jj]);
                    mma16816(S[2*jj+1], qfl[ks], kh4[jj] + 2);
                }
            }
        }

        // --- No-max softmax: P = exp2(S); accumulate partial l ---
#pragma unroll
        for (int j = 0; j < 4; j++) {
            S[j][0] = ex2(S[j][0]);
            S[j][1] = ex2(S[j][1]);
            S[j][2] = ex2(S[j][2]);
            S[j][3] = ex2(S[j][3]);
            l0 += S[j][0] + S[j][1];
            l1 += S[j][2] + S[j][3];
        }

        // --- O += P V (3-term), 32 keys = 2 k16 chunks ---
        {
            int vrow_off = (((lane >> 3) & 1) * 8) + (lane & 7);
            int vcol_off = (lane >> 4) * 16;
#pragma unroll
            for (int t = 0; t < 2; t++) {
                unsigned ph[4], pl[4];
                const float* s0 = S[2 * t];
                const float* s1 = S[2 * t + 1];
                ph[0] = pack_bf16(s0[0], s0[1]);
                ph[1] = pack_bf16(s0[2], s0[3]);
                ph[2] = pack_bf16(s1[0], s1[1]);
                ph[3] = pack_bf16(s1[2], s1[3]);
                pl[0] = pack_bf16(s0[0]-bf16_rn(s0[0]), s0[1]-bf16_rn(s0[1]));
                pl[1] = pack_bf16(s0[2]-bf16_rn(s0[2]), s0[3]-bf16_rn(s0[3]));
                pl[2] = pack_bf16(s1[0]-bf16_rn(s1[0]), s1[1]-bf16_rn(s1[1]));
                pl[3] = pack_bf16(s1[2]-bf16_rn(s1[2]), s1[3]-bf16_rn(s1[3]));
#pragma unroll
                for (int nn = 0; nn < 8; nn += 2) {
                    unsigned vha[4], vla[4], vhb[4], vlb[4];
                    unsigned va = (t * 16 + vrow_off) * A_STR
                                  + nn * 32 + vcol_off;
                    ldsm_x4_t(vha, sVh + va);
                    ldsm_x4_t(vla, sVl + va);
                    ldsm_x4_t(vhb, sVh + va + 32);
                    ldsm_x4_t(vlb, sVl + va + 32);
                    mma16816(O[2*nn],   ph, vha);
                    mma16816(O[2*nn+1], ph, vha + 2);
                    mma16816(O[2*nn+2], ph, vhb);
                    mma16816(O[2*nn+3], ph, vhb + 2);
                    mma16816(O[2*nn],   ph, vla);
                    mma16816(O[2*nn+1], ph, vla + 2);
                    mma16816(O[2*nn+2], ph, vlb);
                    mma16816(O[2*nn+3], ph, vlb + 2);
                    mma16816(O[2*nn],   pl, vha);
                    mma16816(O[2*nn+1], pl, vha + 2);
                    mma16816(O[2*nn+2], pl, vhb);
                    mma16816(O[2*nn+3], pl, vhb + 2);
                }
            }
        }

        if (++buf == 3) buf = 0;
    }

    // --- Final l reduction across the 4 lanes of each row group ---
    l0 += __shfl_xor_sync(0xffffffffu, l0, 1);
    l0 += __shfl_xor_sync(0xffffffffu, l0, 2);
    l1 += __shfl_xor_sync(0xffffffffu, l1, 1);
    l1 += __shfl_xor_sync(0xffffffffu, l1, 2);

    // --- Write output ---
    const int b = bh >> 4, h = bh & 15;
    float inv0 = __fdividef(1.0f, l0);
    float inv1 = __fdividef(1.0f, l1);
    int n0g = q0 + wid * 16 + gr;
    float* o0 = out + ((size_t)b * SEQ + n0g) * DIM + h * HD;
    float* o1 = out + ((size_t)b * SEQ + n0g + 8) * DIM + h * HD;
#pragma unroll
    for (int n = 0; n < 16; n++) {
        int d = n * 8 + qc;
        float2 w0 = make_float2(O[n][0] * inv0, O[n][1] * inv0);
        float2 w1 = make_float2(O[n][2] * inv1, O[n][3] * inv1);
        *(float2*)(o0 + d) = w0;
        *(float2*)(o1 + d) = w1;
    }
}

// ---------------------------------------------------------------------------
extern "C" void kernel_launch(void* const* d_in, const int* in_sizes, int n_in,
                              void* d_out, int out_size)
{
    const float* x    = (const float*)d_in[0];
    const float* rot  = (const float*)d_in[1];
    const float* W    = (const float*)d_in[2];
    const float* bias = (const float*)d_in[3];
    const float* qw   = (const float*)d_in[4];
    const float* kw   = (const float*)d_in[5];
    float* out = (float*)d_out;

    convert_x_kernel<<<(MROWS * DIM) / (256 * 4), 256>>>(x);
    convert_w_kernel<<<dim3(QKV_COLS / 32, DIM / 32), dim3(32, 8)>>>(W);

    cudaFuncSetAttribute(qkv_gemm_mma_kernel,
                         cudaFuncAttributeMaxDynamicSharedMemorySize, GEMM_SMEM);
    qkv_gemm_mma_kernel<<<dim3(QKV_COLS / 256, MROWS / 128), 256, GEMM_SMEM>>>(bias);

    norm_rope_kernel<<<(BATCH * NHEADS * SEQ) / 8, 256>>>(rot, qw, kw);

    cudaFuncSetAttribute(attn_mma_kernel,
                         cudaFuncAttributeMaxDynamicSharedMemorySize, ATT_SMEM);
    attn_mma_kernel<<<dim3(SEQ / 64, BATCH * NHEADS), 128, ATT_SMEM>>>(out);
}

// round 9
// speedup vs baseline: 1.8164x; 1.8164x over previous
#include <cuda_runtime.h>
#include <cuda_fp16.h>
#include <math_constants.h>

#define DIM     2048
#define NHEADS  16
#define HD      128
#define BATCH   2
#define SEQ     4096
#define QKV_COLS (3*DIM)        // 6144
#define MROWS   (BATCH*SEQ)     // 8192

// ---------------------------------------------------------------------------
// Device-global scratch
// ---------------------------------------------------------------------------
__device__ float g_Q[(size_t)BATCH*NHEADS*SEQ*HD];   // pre-norm Q (fp32)
__device__ float g_K[(size_t)BATCH*NHEADS*SEQ*HD];   // pre-norm K (fp32)
__device__ __half g_Qf[(size_t)BATCH*NHEADS*SEQ*HD]; // normed+rope, scaled
__device__ __half g_Kf[(size_t)BATCH*NHEADS*SEQ*HD];
__device__ __half g_Vf[(size_t)BATCH*NHEADS*SEQ*HD];
__device__ __half g_xh[(size_t)MROWS*DIM];           // x hi (fp16)
__device__ __half g_xl[(size_t)MROWS*DIM];           // x lo (fp16)
__device__ __half g_wt[(size_t)QKV_COLS*DIM];        // W^T single fp16

// ---------------------------------------------------------------------------
// PTX helpers (arch-neutral: mma.sync / ldmatrix / cp.async, sm_80+)
// ---------------------------------------------------------------------------
__device__ __forceinline__ unsigned smem_u32(const void* p) {
    unsigned a;
    asm("{ .reg .u64 t; cvta.to.shared.u64 t, %1; cvt.u32.u64 %0, t; }"
        : "=r"(a) : "l"(p));
    return a;
}
__device__ __forceinline__ void ldsm_x4(unsigned r[4], unsigned a) {
    asm volatile("ldmatrix.sync.aligned.m8n8.x4.shared.b16 {%0,%1,%2,%3}, [%4];"
                 : "=r"(r[0]), "=r"(r[1]), "=r"(r[2]), "=r"(r[3]) : "r"(a));
}
__device__ __forceinline__ void ldsm_x4_t(unsigned r[4], unsigned a) {
    asm volatile("ldmatrix.sync.aligned.m8n8.x4.trans.shared.b16 {%0,%1,%2,%3}, [%4];"
                 : "=r"(r[0]), "=r"(r[1]), "=r"(r[2]), "=r"(r[3]) : "r"(a));
}
__device__ __forceinline__ void mma16816(float c[4], const unsigned a[4],
                                         const unsigned b[2]) {
    asm volatile(
        "mma.sync.aligned.m16n8k16.row.col.f32.f16.f16.f32 "
        "{%0,%1,%2,%3}, {%4,%5,%6,%7}, {%8,%9}, {%0,%1,%2,%3};"
        : "+f"(c[0]), "+f"(c[1]), "+f"(c[2]), "+f"(c[3])
        : "r"(a[0]), "r"(a[1]), "r"(a[2]), "r"(a[3]), "r"(b[0]), "r"(b[1]));
}
__device__ __forceinline__ unsigned pack_f16(float lo, float hi) {
    unsigned r;
    asm("cvt.rn.f16x2.f32 %0, %1, %2;" : "=r"(r) : "f"(hi), "f"(lo));
    return r;
}
__device__ __forceinline__ float ex2(float x) {
    float y;
    asm("ex2.approx.f32 %0, %1;" : "=f"(y) : "f"(x));
    return y;
}
__device__ __forceinline__ void cp16(unsigned dst, const void* src) {
    asm volatile("cp.async.cg.shared.global [%0], [%1], 16;"
                 :: "r"(dst), "l"(src));
}
#define CP_COMMIT()  asm volatile("cp.async.commit_group;" ::: "memory")
#define CP_WAIT(n)   asm volatile("cp.async.wait_group %0;" :: "n"(n) : "memory")

// ---------------------------------------------------------------------------
// Kernel 0a: split x (fp32) into fp16 hi/lo
// ---------------------------------------------------------------------------
__global__ void convert_x_kernel(const float* __restrict__ x)
{
    size_t i = ((size_t)blockIdx.x * 256 + threadIdx.x) * 4;
    float4 v = *(const float4*)(x + i);
    float f[4] = {v.x, v.y, v.z, v.w};
    __half h[4], lo[4];
#pragma unroll
    for (int j = 0; j < 4; j++) {
        h[j] = __float2half(f[j]);
        lo[j] = __float2half(f[j] - __half2float(h[j]));
    }
    *(uint2*)(g_xh + i) = *(uint2*)h;
    *(uint2*)(g_xl + i) = *(uint2*)lo;
}

// ---------------------------------------------------------------------------
// Kernel 0b: transpose W [k][n] -> [n][k], single fp16
// ---------------------------------------------------------------------------
__global__ void convert_w_kernel(const float* __restrict__ W)
{
    __shared__ float tile[32][33];
    int tx = threadIdx.x, ty = threadIdx.y;          // block (32, 8)
    int n0 = blockIdx.x * 32, k0 = blockIdx.y * 32;
#pragma unroll
    for (int r = 0; r < 4; r++) {
        int k = k0 + ty + r * 8;
        tile[ty + r * 8][tx] = W[(size_t)k * QKV_COLS + n0 + tx];
    }
    __syncthreads();
#pragma unroll
    for (int r = 0; r < 4; r++) {
        int n = n0 + ty + r * 8;
        int k = k0 + tx;
        g_wt[(size_t)n * DIM + k] = __float2half(tile[tx][ty + r * 8]);
    }
}

// ---------------------------------------------------------------------------
// Kernel 1: QKV GEMM, fp16 2-term (xh*W + xl*W). CTA 128x256, K-chunk 64,
// 3-stage cp.async pipeline. 8 warps, warp tile 32x128. 256 mma/iter.
// ---------------------------------------------------------------------------
#define G_STR    144                // smem row stride bytes (64 fp16 + 16B pad)
#define G_A_ARR  (128*G_STR)        // 18432
#define G_B_ARR  (256*G_STR)        // 36864
#define G_STAGE  (2*G_A_ARR + G_B_ARR)     // 73728 (Ah, Al, B)
#define GEMM_SMEM (3*G_STAGE)       // 221184

__global__ __launch_bounds__(256, 1) void qkv_gemm_mma_kernel(
    const float* __restrict__ bias)
{
    extern __shared__ char smem[];
    const unsigned sbase = smem_u32(smem);
    const int tid = threadIdx.x;
    const int wid = tid >> 5, lane = tid & 31;
    const int warp_m = wid >> 1, warp_n = wid & 1;
    const int gM0 = blockIdx.y << 7;
    const int gN0 = blockIdx.x << 8;
    const int l15 = lane & 15;

    float acc[2][16][4];
#pragma unroll
    for (int i = 0; i < 2; i++)
#pragma unroll
        for (int j = 0; j < 16; j++)
#pragma unroll
            for (int e = 0; e < 4; e++) acc[i][j][e] = 0.f;

    const uint4* xh4 = (const uint4*)g_xh;
    const uint4* xl4 = (const uint4*)g_xl;
    const uint4* wt4 = (const uint4*)g_wt;

    auto stage_load = [&](int st, int it) {
        unsigned sb = sbase + st * G_STAGE;
        int k0 = it * 64;
#pragma unroll
        for (int l = 0; l < 16; l++) {
            int t = tid + (l << 8);                // 0..4095
            if (t < 2048) {                        // A: Ah, Al
                int arr = t >> 10, w = t & 1023;
                int row = w >> 3, c4 = w & 7;
                const uint4* s = arr ? xl4 : xh4;
                size_t gi = (((size_t)(gM0 + row) * DIM + k0) >> 3) + c4;
                cp16(sb + arr * G_A_ARR + row * G_STR + c4 * 16, s + gi);
            } else {                               // B single
                int w = t - 2048;
                int row = w >> 3, c4 = w & 7;
                size_t gi = (((size_t)(gN0 + row) * DIM + k0) >> 3) + c4;
                cp16(sb + 2 * G_A_ARR + row * G_STR + c4 * 16, wt4 + gi);
            }
        }
    };

    const int NIT = DIM / 64;        // 32
    stage_load(0, 0); CP_COMMIT();
    stage_load(1, 1); CP_COMMIT();

    int buf = 0;
    for (int it = 0; it < NIT; ++it) {
        CP_WAIT(1);
        __syncthreads();

        // early prefetch into buffer freed at it-1
        {
            int nb = buf + 2; if (nb >= 3) nb -= 3;
            if (it + 2 < NIT) stage_load(nb, it + 2);
            CP_COMMIT();
        }

        unsigned sb = sbase + buf * G_STAGE;
        unsigned sAh = sb, sAl = sb + G_A_ARR, sB = sb + 2 * G_A_ARR;

#pragma unroll
        for (int ks = 0; ks < 4; ks++) {
            unsigned ah[2][4], al[2][4];
            int acol = ks * 16 + (lane >> 4) * 8;
#pragma unroll
            for (int i = 0; i < 2; i++) {
                int arow = warp_m * 32 + i * 16 + l15;
                ldsm_x4(ah[i], sAh + arow * G_STR + acol * 2);
                ldsm_x4(al[i], sAl + arow * G_STR + acol * 2);
            }
            int brow_off = (lane >> 4) * 8 + (lane & 7);
            int bcol = ks * 16 + ((lane >> 3) & 1) * 8;
#pragma unroll
            for (int jj = 0; jj < 8; jj++) {
                unsigned b4[4];
                unsigned boff = (warp_n * 128 + jj * 16 + brow_off) * G_STR
                                + bcol * 2;
                ldsm_x4(b4, sB + boff);
                mma16816(acc[0][2*jj],   ah[0], b4);
                mma16816(acc[0][2*jj+1], ah[0], b4 + 2);
                mma16816(acc[1][2*jj],   ah[1], b4);
                mma16816(acc[1][2*jj+1], ah[1], b4 + 2);
                mma16816(acc[0][2*jj],   al[0], b4);
                mma16816(acc[0][2*jj+1], al[0], b4 + 2);
                mma16816(acc[1][2*jj],   al[1], b4);
                mma16816(acc[1][2*jj+1], al[1], b4 + 2);
            }
        }
        if (++buf == 3) buf = 0;
        __syncthreads();     // all warps done with this stage before refill
    }

    // Epilogue: bias + de-interleave scatter (Q,K fp32; V fp16)
    const int gr = lane >> 2, qc = (lane & 3) * 2;
#pragma unroll
    for (int i = 0; i < 2; i++) {
        int rbase = gM0 + warp_m * 32 + i * 16 + gr;
#pragma unroll
        for (int half = 0; half < 2; half++) {
            int row = rbase + half * 8;
            int b = row >> 12;
            int n = row & (SEQ - 1);
#pragma unroll
            for (int j = 0; j < 16; j++) {
                int cb = gN0 + warp_n * 128 + j * 8 + qc;
#pragma unroll
                for (int e = 0; e < 2; e++) {
                    int col = cb + e;
                    float v = acc[i][j][half * 2 + e] + __ldg(bias + col);
                    int h = col / 384;
                    int rem = col - h * 384;
                    int d = rem / 3;
                    int jj = rem - 3 * d;
                    size_t off = ((size_t)(b * NHEADS + h) * SEQ + n) * HD + d;
                    if (jj == 0)      g_Q[off] = v;
                    else if (jj == 1) g_K[off] = v;
                    else              g_Vf[off] = __float2half(v);
                }
            }
        }
    }
}

// ---------------------------------------------------------------------------
// Kernel 2: RMSNorm + RoPE, warp-per-row. Outputs single fp16 Q (scaled by
// (1/sqrt(HD))*log2(e)) and fp16 K.
// ---------------------------------------------------------------------------
__global__ __launch_bounds__(256) void norm_rope_kernel(
    const float* __restrict__ rot, const float* __restrict__ qw,
    const float* __restrict__ kw)
{
    const int lane = threadIdx.x & 31;
    const int row = blockIdx.x * 8 + (threadIdx.x >> 5);
    const int n = row & (SEQ - 1);
    const size_t base = (size_t)row * HD + lane * 4;

    float4 q = *(const float4*)(g_Q + base);
    float4 k = *(const float4*)(g_K + base);

    float q2 = q.x*q.x + q.y*q.y + q.z*q.z + q.w*q.w;
    float k2 = k.x*k.x + k.y*k.y + k.z*k.z + k.w*k.w;
#pragma unroll
    for (int off = 16; off; off >>= 1) {
        q2 += __shfl_xor_sync(0xffffffffu, q2, off);
        k2 += __shfl_xor_sync(0xffffffffu, k2, off);
    }
    float qs = rsqrtf(q2 * (1.0f / HD) + 1e-6f);
    float ks = rsqrtf(k2 * (1.0f / HD) + 1e-6f);

    float4 qwv = *(const float4*)(qw + lane * 4);
    float4 kwv = *(const float4*)(kw + lane * 4);

    float qn0 = q.x * qs * qwv.x, qn1 = q.y * qs * qwv.y;
    float qn2 = q.z * qs * qwv.z, qn3 = q.w * qs * qwv.w;
    float kn0 = k.x * ks * kwv.x, kn1 = k.y * ks * kwv.y;
    float kn2 = k.z * ks * kwv.z, kn3 = k.w * ks * kwv.w;

    const float* rp = rot + (size_t)n * 256 + lane * 8;
    float4 rA = *(const float4*)rp;
    float4 rB = *(const float4*)(rp + 4);

    const float scale = 0.08838834764831845f * 1.4426950408889634f;
    float qo0 = (rA.x * qn0 + rA.y * qn1) * scale;
    float qo1 = (rA.z * qn0 + rA.w * qn1) * scale;
    float qo2 = (rB.x * qn2 + rB.y * qn3) * scale;
    float qo3 = (rB.z * qn2 + rB.w * qn3) * scale;
    float ko0 = rA.x * kn0 + rA.y * kn1;
    float ko1 = rA.z * kn0 + rA.w * kn1;
    float ko2 = rB.x * kn2 + rB.y * kn3;
    float ko3 = rB.z * kn2 + rB.w * kn3;

    uint2 qh = make_uint2(pack_f16(qo0, qo1), pack_f16(qo2, qo3));
    uint2 kh = make_uint2(pack_f16(ko0, ko1), pack_f16(ko2, ko3));
    *(uint2*)(g_Qf + base) = qh;
    *(uint2*)(g_Kf + base) = kh;
}

// ---------------------------------------------------------------------------
// Kernel 3: Flash attention, pure fp16 single-term. BM=128 (8 warps),
// BN=64, D=128. Q fragments register-resident; K/V 4-stage cp.async
// pipeline with early prefetch. No-max exp2 softmax, deferred l reduction.
// 128 mma/iter (was 384).
// ---------------------------------------------------------------------------
#define A_STR    272                 // smem row stride bytes (128 fp16 + pad)
#define A_ARR    (64*A_STR)          // 17408 (64-row array)
#define A_QARR   (128*A_STR)         // 34816 (Q tile)
#define A_STAGE  (2*A_ARR)           // K, V = 34816
#define ATT_SMEM (4*A_STAGE)         // 139264

__global__ __launch_bounds__(256, 1) void attn_mma_kernel(float* __restrict__ out)
{
    extern __shared__ char smem[];
    const unsigned sbase = smem_u32(smem);
    const int bh = blockIdx.y;
    const int q0 = blockIdx.x << 7;          // 128 rows per CTA
    const int tid = threadIdx.x;
    const int wid = tid >> 5, lane = tid & 31;
    const int l15 = lane & 15;
    const int gr = lane >> 2, qc = (lane & 3) * 2;

    // --- Load Q tile (128 rows fp16) into stage-0 region ---
    {
        const uint4* Qf4 = (const uint4*)g_Qf;
#pragma unroll
        for (int l = 0; l < 8; l++) {
            int t = tid + (l << 8);            // 0..2047
            int row = t >> 4, c = t & 15;
            size_t gi = (((size_t)bh * SEQ + q0 + row) * HD >> 3) + c;
            cp16(sbase + row * A_STR + c * 16, Qf4 + gi);
        }
    }
    CP_COMMIT();
    CP_WAIT(0);
    __syncthreads();

    // --- Hoist Q fragments to registers (once) ---
    unsigned qf[8][4];
    {
        int arow = wid * 16 + l15;
#pragma unroll
        for (int ks = 0; ks < 8; ks++) {
            int acol = ks * 16 + (lane >> 4) * 8;
            ldsm_x4(qf[ks], sbase + arow * A_STR + acol * 2);
        }
    }
    __syncthreads();   // staging free before K/V pipeline reuses it

    const uint4* Kf4 = (const uint4*)g_Kf;
    const uint4* Vf4 = (const uint4*)g_Vf;

    auto stage_load = [&](int st, int kt) {
        unsigned sb = sbase + st * A_STAGE;
#pragma unroll
        for (int l = 0; l < 8; l++) {
            int t = tid + (l << 8);            // 0..2047
            int arr = t >> 10;                 // 0: K, 1: V
            int w = t & 1023;
            int row = w >> 4, c = w & 15;
            size_t gi = (((size_t)bh * SEQ + kt * 64 + row) * HD >> 3) + c;
            const uint4* s = arr ? Vf4 : Kf4;
            cp16(sb + arr * A_ARR + row * A_STR + c * 16, s + gi);
        }
    };

    float O[16][4];
#pragma unroll
    for (int n = 0; n < 16; n++)
#pragma unroll
        for (int e = 0; e < 4; e++) O[n][e] = 0.f;
    float l0 = 0.f, l1 = 0.f;

    const int NKT = SEQ / 64;   // 64
    stage_load(0, 0); CP_COMMIT();
    stage_load(1, 1); CP_COMMIT();
    stage_load(2, 2); CP_COMMIT();

    int buf = 0;
    for (int kt = 0; kt < NKT; kt++) {
        CP_WAIT(2);
        __syncthreads();        // stage kt visible; all warps done with kt-1

        // Early prefetch into the buffer freed at kt-1.
        {
            int nb = (buf + 3) & 3;
            if (kt + 3 < NKT) stage_load(nb, kt + 3);
            CP_COMMIT();
        }

        unsigned sKf = sbase + buf * A_STAGE;
        unsigned sVf = sKf + A_ARR;

        // --- S = Q K^T (single term) ---
        float S[8][4];
#pragma unroll
        for (int j = 0; j < 8; j++)
#pragma unroll
            for (int e = 0; e < 4; e++) S[j][e] = 0.f;

        {
            int brow_off = (lane >> 4) * 8 + (lane & 7);
            int g_kh = ((lane >> 3) & 1) * 8;
#pragma unroll
            for (int ks = 0; ks < 8; ks++) {
                int bcol = ks * 16 + g_kh;
#pragma unroll
                for (int jj = 0; jj < 4; jj++) {
                    unsigned k4[4];
                    unsigned boff = (jj * 16 + brow_off) * A_STR + bcol * 2;
                    ldsm_x4(k4, sKf + boff);
                    mma16816(S[2*jj],   qf[ks], k4);
                    mma16816(S[2*jj+1], qf[ks], k4 + 2);
                }
            }
        }

        // --- No-max softmax: P = exp2(S); accumulate partial l (fp32) ---
#pragma unroll
        for (int j = 0; j < 8; j++) {
            S[j][0] = ex2(S[j][0]);
            S[j][1] = ex2(S[j][1]);
            S[j][2] = ex2(S[j][2]);
            S[j][3] = ex2(S[j][3]);
            l0 += S[j][0] + S[j][1];
            l1 += S[j][2] + S[j][3];
        }

        // --- O += P V (single term) ---
        {
            int vrow_off = (((lane >> 3) & 1) * 8) + (lane & 7);
            int vcol_off = (lane >> 4) * 16;
#pragma unroll
            for (int t = 0; t < 4; t++) {
                unsigned ph[4];
                const float* s0 = S[2 * t];
                const float* s1 = S[2 * t + 1];
                ph[0] = pack_f16(s0[0], s0[1]);
                ph[1] = pack_f16(s0[2], s0[3]);
                ph[2] = pack_f16(s1[0], s1[1]);
                ph[3] = pack_f16(s1[2], s1[3]);
#pragma unroll
                for (int nn = 0; nn < 8; nn += 2) {
                    unsigned vha[4], vhb[4];
                    unsigned va = (t * 16 + vrow_off) * A_STR
                                  + nn * 32 + vcol_off;
                    ldsm_x4_t(vha, sVf + va);
                    ldsm_x4_t(vhb, sVf + va + 32);
                    mma16816(O[2*nn],   ph, vha);
                    mma16816(O[2*nn+1], ph, vha + 2);
                    mma16816(O[2*nn+2], ph, vhb);
                    mma16816(O[2*nn+3], ph, vhb + 2);
                }
            }
        }

        buf = (buf + 1) & 3;
    }

    // --- Final l reduction across the 4 lanes of each row group ---
    l0 += __shfl_xor_sync(0xffffffffu, l0, 1);
    l0 += __shfl_xor_sync(0xffffffffu, l0, 2);
    l1 += __shfl_xor_sync(0xffffffffu, l1, 1);
    l1 += __shfl_xor_sync(0xffffffffu, l1, 2);

    // --- Write output ---
    const int b = bh >> 4, h = bh & 15;
    float inv0 = __fdividef(1.0f, l0);
    float inv1 = __fdividef(1.0f, l1);
    int n0g = q0 + wid * 16 + gr;
    float* o0 = out + ((size_t)b * SEQ + n0g) * DIM + h * HD;
    float* o1 = out + ((size_t)b * SEQ + n0g + 8) * DIM + h * HD;
#pragma unroll
    for (int n = 0; n < 16; n++) {
        int d = n * 8 + qc;
        float2 w0 = make_float2(O[n][0] * inv0, O[n][1] * inv0);
        float2 w1 = make_float2(O[n][2] * inv1, O[n][3] * inv1);
        *(float2*)(o0 + d) = w0;
        *(float2*)(o1 + d) = w1;
    }
}

// ---------------------------------------------------------------------------
extern "C" void kernel_launch(void* const* d_in, const int* in_sizes, int n_in,
                              void* d_out, int out_size)
{
    const float* x    = (const float*)d_in[0];
    const float* rot  = (const float*)d_in[1];
    const float* W    = (const float*)d_in[2];
    const float* bias = (const float*)d_in[3];
    const float* qw   = (const float*)d_in[4];
    const float* kw   = (const float*)d_in[5];
    float* out = (float*)d_out;

    convert_x_kernel<<<(MROWS * DIM) / (256 * 4), 256>>>(x);
    convert_w_kernel<<<dim3(QKV_COLS / 32, DIM / 32), dim3(32, 8)>>>(W);

    cudaFuncSetAttribute(qkv_gemm_mma_kernel,
                         cudaFuncAttributeMaxDynamicSharedMemorySize, GEMM_SMEM);
    qkv_gemm_mma_kernel<<<dim3(QKV_COLS / 256, MROWS / 128), 256, GEMM_SMEM>>>(bias);

    norm_rope_kernel<<<(BATCH * NHEADS * SEQ) / 8, 256>>>(rot, qw, kw);

    cudaFuncSetAttribute(attn_mma_kernel,
                         cudaFuncAttributeMaxDynamicSharedMemorySize, ATT_SMEM);
    attn_mma_kernel<<<dim3(SEQ / 128, BATCH * NHEADS), 256, ATT_SMEM>>>(out);
}

// round 10
// speedup vs baseline: 2.2809x; 1.2557x over previous
#include <cuda_runtime.h>
#include <cuda_fp16.h>
#include <math_constants.h>

#define DIM     2048
#define NHEADS  16
#define HD      128
#define BATCH   2
#define SEQ     4096
#define QKV_COLS (3*DIM)        // 6144
#define MROWS   (BATCH*SEQ)     // 8192

// ---------------------------------------------------------------------------
// Device-global scratch
// ---------------------------------------------------------------------------
__device__ float g_Q[(size_t)BATCH*NHEADS*SEQ*HD];   // pre-norm Q (fp32)
__device__ float g_K[(size_t)BATCH*NHEADS*SEQ*HD];   // pre-norm K (fp32)
__device__ __half g_Qf[(size_t)BATCH*NHEADS*SEQ*HD]; // normed+rope, scaled
__device__ __half g_Kf[(size_t)BATCH*NHEADS*SEQ*HD];
__device__ __half g_Vf[(size_t)BATCH*NHEADS*SEQ*HD];
__device__ __half g_xh[(size_t)MROWS*DIM];           // x (fp16)
__device__ __half g_wt[(size_t)QKV_COLS*DIM];        // W^T (fp16)

// ---------------------------------------------------------------------------
// PTX helpers (arch-neutral: mma.sync / ldmatrix / cp.async, sm_80+)
// ---------------------------------------------------------------------------
__device__ __forceinline__ unsigned smem_u32(const void* p) {
    unsigned a;
    asm("{ .reg .u64 t; cvta.to.shared.u64 t, %1; cvt.u32.u64 %0, t; }"
        : "=r"(a) : "l"(p));
    return a;
}
__device__ __forceinline__ void ldsm_x4(unsigned r[4], unsigned a) {
    asm volatile("ldmatrix.sync.aligned.m8n8.x4.shared.b16 {%0,%1,%2,%3}, [%4];"
                 : "=r"(r[0]), "=r"(r[1]), "=r"(r[2]), "=r"(r[3]) : "r"(a));
}
__device__ __forceinline__ void ldsm_x4_t(unsigned r[4], unsigned a) {
    asm volatile("ldmatrix.sync.aligned.m8n8.x4.trans.shared.b16 {%0,%1,%2,%3}, [%4];"
                 : "=r"(r[0]), "=r"(r[1]), "=r"(r[2]), "=r"(r[3]) : "r"(a));
}
__device__ __forceinline__ void mma16816(float c[4], const unsigned a[4],
                                         const unsigned b[2]) {
    asm volatile(
        "mma.sync.aligned.m16n8k16.row.col.f32.f16.f16.f32 "
        "{%0,%1,%2,%3}, {%4,%5,%6,%7}, {%8,%9}, {%0,%1,%2,%3};"
        : "+f"(c[0]), "+f"(c[1]), "+f"(c[2]), "+f"(c[3])
        : "r"(a[0]), "r"(a[1]), "r"(a[2]), "r"(a[3]), "r"(b[0]), "r"(b[1]));
}
__device__ __forceinline__ unsigned pack_f16(float lo, float hi) {
    unsigned r;
    asm("cvt.rn.f16x2.f32 %0, %1, %2;" : "=r"(r) : "f"(hi), "f"(lo));
    return r;
}
__device__ __forceinline__ float ex2(float x) {
    float y;
    asm("ex2.approx.f32 %0, %1;" : "=f"(y) : "f"(x));
    return y;
}
__device__ __forceinline__ void cp16(unsigned dst, const void* src) {
    asm volatile("cp.async.cg.shared.global [%0], [%1], 16;"
                 :: "r"(dst), "l"(src));
}
#define CP_COMMIT()  asm volatile("cp.async.commit_group;" ::: "memory")
#define CP_WAIT(n)   asm volatile("cp.async.wait_group %0;" :: "n"(n) : "memory")

// ---------------------------------------------------------------------------
// Kernel 0a: convert x (fp32) to fp16
// ---------------------------------------------------------------------------
__global__ void convert_x_kernel(const float* __restrict__ x)
{
    size_t i = ((size_t)blockIdx.x * 256 + threadIdx.x) * 8;
    float4 v0 = *(const float4*)(x + i);
    float4 v1 = *(const float4*)(x + i + 4);
    uint4 o;
    o.x = pack_f16(v0.x, v0.y);
    o.y = pack_f16(v0.z, v0.w);
    o.z = pack_f16(v1.x, v1.y);
    o.w = pack_f16(v1.z, v1.w);
    *(uint4*)(g_xh + i) = o;
}

// ---------------------------------------------------------------------------
// Kernel 0b: transpose W [k][n] -> [n][k], fp16
// ---------------------------------------------------------------------------
__global__ void convert_w_kernel(const float* __restrict__ W)
{
    __shared__ float tile[32][33];
    int tx = threadIdx.x, ty = threadIdx.y;          // block (32, 8)
    int n0 = blockIdx.x * 32, k0 = blockIdx.y * 32;
#pragma unroll
    for (int r = 0; r < 4; r++) {
        int k = k0 + ty + r * 8;
        tile[ty + r * 8][tx] = W[(size_t)k * QKV_COLS + n0 + tx];
    }
    __syncthreads();
#pragma unroll
    for (int r = 0; r < 4; r++) {
        int n = n0 + ty + r * 8;
        int k = k0 + tx;
        g_wt[(size_t)n * DIM + k] = __float2half(tile[tx][ty + r * 8]);
    }
}

// ---------------------------------------------------------------------------
// Kernel 1: QKV GEMM, single-term fp16. CTA 128x256, K-chunk 64,
// 4-stage cp.async pipeline. 8 warps, warp tile 32x128. 128 mma/iter.
// ---------------------------------------------------------------------------
#define G_STR    144                // smem row stride bytes (64 fp16 + 16B pad)
#define G_A_ARR  (128*G_STR)        // 18432
#define G_B_ARR  (256*G_STR)        // 36864
#define G_STAGE  (G_A_ARR + G_B_ARR)       // 55296
#define GEMM_SMEM (4*G_STAGE)       // 221184

__global__ __launch_bounds__(256, 1) void qkv_gemm_mma_kernel(
    const float* __restrict__ bias)
{
    extern __shared__ char smem[];
    const unsigned sbase = smem_u32(smem);
    const int tid = threadIdx.x;
    const int wid = tid >> 5, lane = tid & 31;
    const int warp_m = wid >> 1, warp_n = wid & 1;
    const int gM0 = blockIdx.y << 7;
    const int gN0 = blockIdx.x << 8;
    const int l15 = lane & 15;

    float acc[2][16][4];
#pragma unroll
    for (int i = 0; i < 2; i++)
#pragma unroll
        for (int j = 0; j < 16; j++)
#pragma unroll
            for (int e = 0; e < 4; e++) acc[i][j][e] = 0.f;

    const uint4* xh4 = (const uint4*)g_xh;
    const uint4* wt4 = (const uint4*)g_wt;

    auto stage_load = [&](int st, int it) {
        unsigned sb = sbase + st * G_STAGE;
        int k0 = it * 64;
#pragma unroll
        for (int l = 0; l < 12; l++) {
            int t = tid + (l << 8);                // 0..3071
            if (t < 1024) {                        // A
                int row = t >> 3, c4 = t & 7;
                size_t gi = (((size_t)(gM0 + row) * DIM + k0) >> 3) + c4;
                cp16(sb + row * G_STR + c4 * 16, xh4 + gi);
            } else {                               // B
                int w = t - 1024;
                int row = w >> 3, c4 = w & 7;
                size_t gi = (((size_t)(gN0 + row) * DIM + k0) >> 3) + c4;
                cp16(sb + G_A_ARR + row * G_STR + c4 * 16, wt4 + gi);
            }
        }
    };

    const int NIT = DIM / 64;        // 32
    stage_load(0, 0); CP_COMMIT();
    stage_load(1, 1); CP_COMMIT();
    stage_load(2, 2); CP_COMMIT();

    int buf = 0;
    for (int it = 0; it < NIT; ++it) {
        CP_WAIT(2);
        __syncthreads();

        // early prefetch into buffer freed at it-1
        {
            int nb = (buf + 3) & 3;
            if (it + 3 < NIT) stage_load(nb, it + 3);
            CP_COMMIT();
        }

        unsigned sb = sbase + buf * G_STAGE;
        unsigned sA = sb, sB = sb + G_A_ARR;

#pragma unroll
        for (int ks = 0; ks < 4; ks++) {
            unsigned a4[2][4];
            int acol = ks * 16 + (lane >> 4) * 8;
#pragma unroll
            for (int i = 0; i < 2; i++) {
                int arow = warp_m * 32 + i * 16 + l15;
                ldsm_x4(a4[i], sA + arow * G_STR + acol * 2);
            }
            int brow_off = (lane >> 4) * 8 + (lane & 7);
            int bcol = ks * 16 + ((lane >> 3) & 1) * 8;
#pragma unroll
            for (int jj = 0; jj < 8; jj++) {
                unsigned b4[4];
                unsigned boff = (warp_n * 128 + jj * 16 + brow_off) * G_STR
                                + bcol * 2;
                ldsm_x4(b4, sB + boff);
                mma16816(acc[0][2*jj],   a4[0], b4);
                mma16816(acc[0][2*jj+1], a4[0], b4 + 2);
                mma16816(acc[1][2*jj],   a4[1], b4);
                mma16816(acc[1][2*jj+1], a4[1], b4 + 2);
            }
        }
        buf = (buf + 1) & 3;
        __syncthreads();     // all warps done with this stage before refill
    }

    // Epilogue: bias + de-interleave scatter (Q,K fp32; V fp16)
    const int gr = lane >> 2, qc = (lane & 3) * 2;
#pragma unroll
    for (int i = 0; i < 2; i++) {
        int rbase = gM0 + warp_m * 32 + i * 16 + gr;
#pragma unroll
        for (int half = 0; half < 2; half++) {
            int row = rbase + half * 8;
            int b = row >> 12;
            int n = row & (SEQ - 1);
#pragma unroll
            for (int j = 0; j < 16; j++) {
                int cb = gN0 + warp_n * 128 + j * 8 + qc;
#pragma unroll
                for (int e = 0; e < 2; e++) {
                    int col = cb + e;
                    float v = acc[i][j][half * 2 + e] + __ldg(bias + col);
                    int h = col / 384;
                    int rem = col - h * 384;
                    int d = rem / 3;
                    int jj = rem - 3 * d;
                    size_t off = ((size_t)(b * NHEADS + h) * SEQ + n) * HD + d;
                    if (jj == 0)      g_Q[off] = v;
                    else if (jj == 1) g_K[off] = v;
                    else              g_Vf[off] = __float2half(v);
                }
            }
        }
    }
}

// ---------------------------------------------------------------------------
// Kernel 2: RMSNorm + RoPE, warp-per-row. Outputs fp16 Q (scaled by
// (1/sqrt(HD))*log2(e)) and fp16 K.
// ---------------------------------------------------------------------------
__global__ __launch_bounds__(256) void norm_rope_kernel(
    const float* __restrict__ rot, const float* __restrict__ qw,
    const float* __restrict__ kw)
{
    const int lane = threadIdx.x & 31;
    const int row = blockIdx.x * 8 + (threadIdx.x >> 5);
    const int n = row & (SEQ - 1);
    const size_t base = (size_t)row * HD + lane * 4;

    float4 q = *(const float4*)(g_Q + base);
    float4 k = *(const float4*)(g_K + base);

    float q2 = q.x*q.x + q.y*q.y + q.z*q.z + q.w*q.w;
    float k2 = k.x*k.x + k.y*k.y + k.z*k.z + k.w*k.w;
#pragma unroll
    for (int off = 16; off; off >>= 1) {
        q2 += __shfl_xor_sync(0xffffffffu, q2, off);
        k2 += __shfl_xor_sync(0xffffffffu, k2, off);
    }
    float qs = rsqrtf(q2 * (1.0f / HD) + 1e-6f);
    float ks = rsqrtf(k2 * (1.0f / HD) + 1e-6f);

    float4 qwv = *(const float4*)(qw + lane * 4);
    float4 kwv = *(const float4*)(kw + lane * 4);

    float qn0 = q.x * qs * qwv.x, qn1 = q.y * qs * qwv.y;
    float qn2 = q.z * qs * qwv.z, qn3 = q.w * qs * qwv.w;
    float kn0 = k.x * ks * kwv.x, kn1 = k.y * ks * kwv.y;
    float kn2 = k.z * ks * kwv.z, kn3 = k.w * ks * kwv.w;

    const float* rp = rot + (size_t)n * 256 + lane * 8;
    float4 rA = *(const float4*)rp;
    float4 rB = *(const float4*)(rp + 4);

    const float scale = 0.08838834764831845f * 1.4426950408889634f;
    float qo0 = (rA.x * qn0 + rA.y * qn1) * scale;
    float qo1 = (rA.z * qn0 + rA.w * qn1) * scale;
    float qo2 = (rB.x * qn2 + rB.y * qn3) * scale;
    float qo3 = (rB.z * qn2 + rB.w * qn3) * scale;
    float ko0 = rA.x * kn0 + rA.y * kn1;
    float ko1 = rA.z * kn0 + rA.w * kn1;
    float ko2 = rB.x * kn2 + rB.y * kn3;
    float ko3 = rB.z * kn2 + rB.w * kn3;

    uint2 qh = make_uint2(pack_f16(qo0, qo1), pack_f16(qo2, qo3));
    uint2 kh = make_uint2(pack_f16(ko0, ko1), pack_f16(ko2, ko3));
    *(uint2*)(g_Qf + base) = qh;
    *(uint2*)(g_Kf + base) = kh;
}

// ---------------------------------------------------------------------------
// Kernel 3: Flash attention, pure fp16 single-term. BM=128 (8 warps),
// BN=64, D=128. Q fragments register-resident; K/V 4-stage cp.async
// pipeline with early prefetch. No-max exp2 softmax, deferred l reduction.
// ---------------------------------------------------------------------------
#define A_STR    272                 // smem row stride bytes (128 fp16 + pad)
#define A_ARR    (64*A_STR)          // 17408 (64-row array)
#define A_STAGE  (2*A_ARR)           // K, V = 34816
#define ATT_SMEM (4*A_STAGE)         // 139264

__global__ __launch_bounds__(256, 1) void attn_mma_kernel(float* __restrict__ out)
{
    extern __shared__ char smem[];
    const unsigned sbase = smem_u32(smem);
    const int bh = blockIdx.y;
    const int q0 = blockIdx.x << 7;          // 128 rows per CTA
    const int tid = threadIdx.x;
    const int wid = tid >> 5, lane = tid & 31;
    const int l15 = lane & 15;
    const int gr = lane >> 2, qc = (lane & 3) * 2;

    // --- Load Q tile (128 rows fp16) into stage-0 region ---
    {
        const uint4* Qf4 = (const uint4*)g_Qf;
#pragma unroll
        for (int l = 0; l < 8; l++) {
            int t = tid + (l << 8);            // 0..2047
            int row = t >> 4, c = t & 15;
            size_t gi = (((size_t)bh * SEQ + q0 + row) * HD >> 3) + c;
            cp16(sbase + row * A_STR + c * 16, Qf4 + gi);
        }
    }
    CP_COMMIT();
    CP_WAIT(0);
    __syncthreads();

    // --- Hoist Q fragments to registers (once) ---
    unsigned qf[8][4];
    {
        int arow = wid * 16 + l15;
#pragma unroll
        for (int ks = 0; ks < 8; ks++) {
            int acol = ks * 16 + (lane >> 4) * 8;
            ldsm_x4(qf[ks], sbase + arow * A_STR + acol * 2);
        }
    }
    __syncthreads();   // staging free before K/V pipeline reuses it

    const uint4* Kf4 = (const uint4*)g_Kf;
    const uint4* Vf4 = (const uint4*)g_Vf;

    auto stage_load = [&](int st, int kt) {
        unsigned sb = sbase + st * A_STAGE;
#pragma unroll
        for (int l = 0; l < 8; l++) {
            int t = tid + (l << 8);            // 0..2047
            int arr = t >> 10;                 // 0: K, 1: V
            int w = t & 1023;
            int row = w >> 4, c = w & 15;
            size_t gi = (((size_t)bh * SEQ + kt * 64 + row) * HD >> 3) + c;
            const uint4* s = arr ? Vf4 : Kf4;
            cp16(sb + arr * A_ARR + row * A_STR + c * 16, s + gi);
        }
    };

    float O[16][4];
#pragma unroll
    for (int n = 0; n < 16; n++)
#pragma unroll
        for (int e = 0; e < 4; e++) O[n][e] = 0.f;
    float l0 = 0.f, l1 = 0.f;

    const int NKT = SEQ / 64;   // 64
    stage_load(0, 0); CP_COMMIT();
    stage_load(1, 1); CP_COMMIT();
    stage_load(2, 2); CP_COMMIT();

    int buf = 0;
    for (int kt = 0; kt < NKT; kt++) {
        CP_WAIT(2);
        __syncthreads();        // stage kt visible; all warps done with kt-1

        // Early prefetch into the buffer freed at kt-1.
        {
            int nb = (buf + 3) & 3;
            if (kt + 3 < NKT) stage_load(nb, kt + 3);
            CP_COMMIT();
        }

        unsigned sKf = sbase + buf * A_STAGE;
        unsigned sVf = sKf + A_ARR;

        // --- S = Q K^T (single term) ---
        float S[8][4];
#pragma unroll
        for (int j = 0; j < 8; j++)
#pragma unroll
            for (int e = 0; e < 4; e++) S[j][e] = 0.f;

        {
            int brow_off = (lane >> 4) * 8 + (lane & 7);
            int g_kh = ((lane >> 3) & 1) * 8;
#pragma unroll
            for (int ks = 0; ks < 8; ks++) {
                int bcol = ks * 16 + g_kh;
#pragma unroll
                for (int jj = 0; jj < 4; jj++) {
                    unsigned k4[4];
                    unsigned boff = (jj * 16 + brow_off) * A_STR + bcol * 2;
                    ldsm_x4(k4, sKf + boff);
                    mma16816(S[2*jj],   qf[ks], k4);
                    mma16816(S[2*jj+1], qf[ks], k4 + 2);
                }
            }
        }

        // --- No-max softmax: P = exp2(S); accumulate partial l (fp32) ---
#pragma unroll
        for (int j = 0; j < 8; j++) {
            S[j][0] = ex2(S[j][0]);
            S[j][1] = ex2(S[j][1]);
            S[j][2] = ex2(S[j][2]);
            S[j][3] = ex2(S[j][3]);
            l0 += S[j][0] + S[j][1];
            l1 += S[j][2] + S[j][3];
        }

        // --- O += P V (single term) ---
        {
            int vrow_off = (((lane >> 3) & 1) * 8) + (lane & 7);
            int vcol_off = (lane >> 4) * 16;
#pragma unroll
            for (int t = 0; t < 4; t++) {
                unsigned ph[4];
                const float* s0 = S[2 * t];
                const float* s1 = S[2 * t + 1];
                ph[0] = pack_f16(s0[0], s0[1]);
                ph[1] = pack_f16(s0[2], s0[3]);
                ph[2] = pack_f16(s1[0], s1[1]);
                ph[3] = pack_f16(s1[2], s1[3]);
#pragma unroll
                for (int nn = 0; nn < 8; nn += 2) {
                    unsigned vha[4], vhb[4];
                    unsigned va = (t * 16 + vrow_off) * A_STR
                                  + nn * 32 + vcol_off;
                    ldsm_x4_t(vha, sVf + va);
                    ldsm_x4_t(vhb, sVf + va + 32);
                    mma16816(O[2*nn],   ph, vha);
                    mma16816(O[2*nn+1], ph, vha + 2);
                    mma16816(O[2*nn+2], ph, vhb);
                    mma16816(O[2*nn+3], ph, vhb + 2);
                }
            }
        }

        buf = (buf + 1) & 3;
    }

    // --- Final l reduction across the 4 lanes of each row group ---
    l0 += __shfl_xor_sync(0xffffffffu, l0, 1);
    l0 += __shfl_xor_sync(0xffffffffu, l0, 2);
    l1 += __shfl_xor_sync(0xffffffffu, l1, 1);
    l1 += __shfl_xor_sync(0xffffffffu, l1, 2);

    // --- Write output ---
    const int b = bh >> 4, h = bh & 15;
    float inv0 = __fdividef(1.0f, l0);
    float inv1 = __fdividef(1.0f, l1);
    int n0g = q0 + wid * 16 + gr;
    float* o0 = out + ((size_t)b * SEQ + n0g) * DIM + h * HD;
    float* o1 = out + ((size_t)b * SEQ + n0g + 8) * DIM + h * HD;
#pragma unroll
    for (int n = 0; n < 16; n++) {
        int d = n * 8 + qc;
        float2 w0 = make_float2(O[n][0] * inv0, O[n][1] * inv0);
        float2 w1 = make_float2(O[n][2] * inv1, O[n][3] * inv1);
        *(float2*)(o0 + d) = w0;
        *(float2*)(o1 + d) = w1;
    }
}

// ---------------------------------------------------------------------------
extern "C" void kernel_launch(void* const* d_in, const int* in_sizes, int n_in,
                              void* d_out, int out_size)
{
    const float* x    = (const float*)d_in[0];
    const float* rot  = (const float*)d_in[1];
    const float* W    = (const float*)d_in[2];
    const float* bias = (const float*)d_in[3];
    const float* qw   = (const float*)d_in[4];
    const float* kw   = (const float*)d_in[5];
    float* out = (float*)d_out;

    convert_x_kernel<<<(MROWS * DIM) / (256 * 8), 256>>>(x);
    convert_w_kernel<<<dim3(QKV_COLS / 32, DIM / 32), dim3(32, 8)>>>(W);

    cudaFuncSetAttribute(qkv_gemm_mma_kernel,
                         cudaFuncAttributeMaxDynamicSharedMemorySize, GEMM_SMEM);
    qkv_gemm_mma_kernel<<<dim3(QKV_COLS / 256, MROWS / 128), 256, GEMM_SMEM>>>(bias);

    norm_rope_kernel<<<(BATCH * NHEADS * SEQ) / 8, 256>>>(rot, qw, kw);

    cudaFuncSetAttribute(attn_mma_kernel,
                         cudaFuncAttributeMaxDynamicSharedMemorySize, ATT_SMEM);
    attn_mma_kernel<<<dim3(SEQ / 128, BATCH * NHEADS), 256, ATT_SMEM>>>(out);
}

// round 11
// speedup vs baseline: 2.2935x; 1.0055x over previous
#include <cuda_runtime.h>
#include <cuda_fp16.h>
#include <math_constants.h>

#define DIM     2048
#define NHEADS  16
#define HD      128
#define BATCH   2
#define SEQ     4096
#define QKV_COLS (3*DIM)        // 6144
#define MROWS   (BATCH*SEQ)     // 8192

// ---------------------------------------------------------------------------
// Device-global scratch
// ---------------------------------------------------------------------------
__device__ float g_Q[(size_t)BATCH*NHEADS*SEQ*HD];   // pre-norm Q (fp32)
__device__ float g_K[(size_t)BATCH*NHEADS*SEQ*HD];   // pre-norm K (fp32)
__device__ __half g_Qf[(size_t)BATCH*NHEADS*SEQ*HD]; // normed+rope, scaled
__device__ __half g_Kf[(size_t)BATCH*NHEADS*SEQ*HD];
__device__ __half g_Vf[(size_t)BATCH*NHEADS*SEQ*HD];
__device__ __half g_xh[(size_t)MROWS*DIM];           // x (fp16)
__device__ __half g_wt[(size_t)QKV_COLS*DIM];        // W^T (fp16)

// ---------------------------------------------------------------------------
// PTX helpers (arch-neutral: mma.sync / ldmatrix / cp.async, sm_80+)
// ---------------------------------------------------------------------------
__device__ __forceinline__ unsigned smem_u32(const void* p) {
    unsigned a;
    asm("{ .reg .u64 t; cvta.to.shared.u64 t, %1; cvt.u32.u64 %0, t; }"
        : "=r"(a) : "l"(p));
    return a;
}
__device__ __forceinline__ void ldsm_x4(unsigned r[4], unsigned a) {
    asm volatile("ldmatrix.sync.aligned.m8n8.x4.shared.b16 {%0,%1,%2,%3}, [%4];"
                 : "=r"(r[0]), "=r"(r[1]), "=r"(r[2]), "=r"(r[3]) : "r"(a));
}
__device__ __forceinline__ void ldsm_x4_t(unsigned r[4], unsigned a) {
    asm volatile("ldmatrix.sync.aligned.m8n8.x4.trans.shared.b16 {%0,%1,%2,%3}, [%4];"
                 : "=r"(r[0]), "=r"(r[1]), "=r"(r[2]), "=r"(r[3]) : "r"(a));
}
__device__ __forceinline__ void mma16816(float c[4], const unsigned a[4],
                                         const unsigned b[2]) {
    asm volatile(
        "mma.sync.aligned.m16n8k16.row.col.f32.f16.f16.f32 "
        "{%0,%1,%2,%3}, {%4,%5,%6,%7}, {%8,%9}, {%0,%1,%2,%3};"
        : "+f"(c[0]), "+f"(c[1]), "+f"(c[2]), "+f"(c[3])
        : "r"(a[0]), "r"(a[1]), "r"(a[2]), "r"(a[3]), "r"(b[0]), "r"(b[1]));
}
__device__ __forceinline__ unsigned pack_f16(float lo, float hi) {
    unsigned r;
    asm("cvt.rn.f16x2.f32 %0, %1, %2;" : "=r"(r) : "f"(hi), "f"(lo));
    return r;
}
__device__ __forceinline__ float ex2(float x) {
    float y;
    asm("ex2.approx.f32 %0, %1;" : "=f"(y) : "f"(x));
    return y;
}
__device__ __forceinline__ void cp16(unsigned dst, const void* src) {
    asm volatile("cp.async.cg.shared.global [%0], [%1], 16;"
                 :: "r"(dst), "l"(src));
}
#define CP_COMMIT()  asm volatile("cp.async.commit_group;" ::: "memory")
#define CP_WAIT(n)   asm volatile("cp.async.wait_group %0;" :: "n"(n) : "memory")

// ---------------------------------------------------------------------------
// Kernel 0a: convert x (fp32) to fp16
// ---------------------------------------------------------------------------
__global__ void convert_x_kernel(const float* __restrict__ x)
{
    size_t i = ((size_t)blockIdx.x * 256 + threadIdx.x) * 8;
    float4 v0 = *(const float4*)(x + i);
    float4 v1 = *(const float4*)(x + i + 4);
    uint4 o;
    o.x = pack_f16(v0.x, v0.y);
    o.y = pack_f16(v0.z, v0.w);
    o.z = pack_f16(v1.x, v1.y);
    o.w = pack_f16(v1.z, v1.w);
    *(uint4*)(g_xh + i) = o;
}

// ---------------------------------------------------------------------------
// Kernel 0b: transpose W [k][n] -> [n][k], fp16
// ---------------------------------------------------------------------------
__global__ void convert_w_kernel(const float* __restrict__ W)
{
    __shared__ float tile[32][33];
    int tx = threadIdx.x, ty = threadIdx.y;          // block (32, 8)
    int n0 = blockIdx.x * 32, k0 = blockIdx.y * 32;
#pragma unroll
    for (int r = 0; r < 4; r++) {
        int k = k0 + ty + r * 8;
        tile[ty + r * 8][tx] = W[(size_t)k * QKV_COLS + n0 + tx];
    }
    __syncthreads();
#pragma unroll
    for (int r = 0; r < 4; r++) {
        int n = n0 + ty + r * 8;
        int k = k0 + tx;
        g_wt[(size_t)n * DIM + k] = __float2half(tile[tx][ty + r * 8]);
    }
}

// ---------------------------------------------------------------------------
// Kernel 1: QKV GEMM, single-term fp16. CTA 128x256, K-chunk 64,
// 4-stage cp.async pipeline, ONE barrier per iteration (early prefetch
// into the buffer the top barrier just freed). 8 warps, 128 mma/iter.
// ---------------------------------------------------------------------------
#define G_STR    144                // smem row stride bytes (64 fp16 + 16B pad)
#define G_A_ARR  (128*G_STR)        // 18432
#define G_B_ARR  (256*G_STR)        // 36864
#define G_STAGE  (G_A_ARR + G_B_ARR)       // 55296
#define GEMM_SMEM (4*G_STAGE)       // 221184

__global__ __launch_bounds__(256, 1) void qkv_gemm_mma_kernel(
    const float* __restrict__ bias)
{
    extern __shared__ char smem[];
    const unsigned sbase = smem_u32(smem);
    const int tid = threadIdx.x;
    const int wid = tid >> 5, lane = tid & 31;
    const int warp_m = wid >> 1, warp_n = wid & 1;
    const int gM0 = blockIdx.y << 7;
    const int gN0 = blockIdx.x << 8;
    const int l15 = lane & 15;

    float acc[2][16][4];
#pragma unroll
    for (int i = 0; i < 2; i++)
#pragma unroll
        for (int j = 0; j < 16; j++)
#pragma unroll
            for (int e = 0; e < 4; e++) acc[i][j][e] = 0.f;

    const uint4* xh4 = (const uint4*)g_xh;
    const uint4* wt4 = (const uint4*)g_wt;

    auto stage_load = [&](int st, int it) {
        unsigned sb = sbase + st * G_STAGE;
        int k0 = it * 64;
#pragma unroll
        for (int l = 0; l < 12; l++) {
            int t = tid + (l << 8);                // 0..3071
            if (t < 1024) {                        // A
                int row = t >> 3, c4 = t & 7;
                size_t gi = (((size_t)(gM0 + row) * DIM + k0) >> 3) + c4;
                cp16(sb + row * G_STR + c4 * 16, xh4 + gi);
            } else {                               // B
                int w = t - 1024;
                int row = w >> 3, c4 = w & 7;
                size_t gi = (((size_t)(gN0 + row) * DIM + k0) >> 3) + c4;
                cp16(sb + G_A_ARR + row * G_STR + c4 * 16, wt4 + gi);
            }
        }
    };

    const int NIT = DIM / 64;        // 32
    stage_load(0, 0); CP_COMMIT();
    stage_load(1, 1); CP_COMMIT();
    stage_load(2, 2); CP_COMMIT();

    int buf = 0;
    for (int it = 0; it < NIT; ++it) {
        CP_WAIT(2);
        __syncthreads();     // stage it visible; all warps finished it-1

        // Early prefetch: buffer (buf+3)&3 held it-1, freed by the barrier.
        {
            int nb = (buf + 3) & 3;
            if (it + 3 < NIT) stage_load(nb, it + 3);
            CP_COMMIT();
        }

        unsigned sb = sbase + buf * G_STAGE;
        unsigned sA = sb, sB = sb + G_A_ARR;

#pragma unroll
        for (int ks = 0; ks < 4; ks++) {
            unsigned a4[2][4];
            int acol = ks * 16 + (lane >> 4) * 8;
#pragma unroll
            for (int i = 0; i < 2; i++) {
                int arow = warp_m * 32 + i * 16 + l15;
                ldsm_x4(a4[i], sA + arow * G_STR + acol * 2);
            }
            int brow_off = (lane >> 4) * 8 + (lane & 7);
            int bcol = ks * 16 + ((lane >> 3) & 1) * 8;
#pragma unroll
            for (int jj = 0; jj < 8; jj++) {
                unsigned b4[4];
                unsigned boff = (warp_n * 128 + jj * 16 + brow_off) * G_STR
                                + bcol * 2;
                ldsm_x4(b4, sB + boff);
                mma16816(acc[0][2*jj],   a4[0], b4);
                mma16816(acc[0][2*jj+1], a4[0], b4 + 2);
                mma16816(acc[1][2*jj],   a4[1], b4);
                mma16816(acc[1][2*jj+1], a4[1], b4 + 2);
            }
        }
        buf = (buf + 1) & 3;
    }

    // Epilogue: bias + de-interleave scatter (Q,K fp32; V fp16)
    const int gr = lane >> 2, qc = (lane & 3) * 2;
#pragma unroll
    for (int i = 0; i < 2; i++) {
        int rbase = gM0 + warp_m * 32 + i * 16 + gr;
#pragma unroll
        for (int half = 0; half < 2; half++) {
            int row = rbase + half * 8;
            int b = row >> 12;
            int n = row & (SEQ - 1);
#pragma unroll
            for (int j = 0; j < 16; j++) {
                int cb = gN0 + warp_n * 128 + j * 8 + qc;
#pragma unroll
                for (int e = 0; e < 2; e++) {
                    int col = cb + e;
                    float v = acc[i][j][half * 2 + e] + __ldg(bias + col);
                    int h = col / 384;
                    int rem = col - h * 384;
                    int d = rem / 3;
                    int jj = rem - 3 * d;
                    size_t off = ((size_t)(b * NHEADS + h) * SEQ + n) * HD + d;
                    if (jj == 0)      g_Q[off] = v;
                    else if (jj == 1) g_K[off] = v;
                    else              g_Vf[off] = __float2half(v);
                }
            }
        }
    }
}

// ---------------------------------------------------------------------------
// Kernel 2: RMSNorm + RoPE, warp-per-row. Outputs fp16 Q (scaled by
// (1/sqrt(HD))*log2(e)) and fp16 K.
// ---------------------------------------------------------------------------
__global__ __launch_bounds__(256) void norm_rope_kernel(
    const float* __restrict__ rot, const float* __restrict__ qw,
    const float* __restrict__ kw)
{
    const int lane = threadIdx.x & 31;
    const int row = blockIdx.x * 8 + (threadIdx.x >> 5);
    const int n = row & (SEQ - 1);
    const size_t base = (size_t)row * HD + lane * 4;

    float4 q = *(const float4*)(g_Q + base);
    float4 k = *(const float4*)(g_K + base);

    float q2 = q.x*q.x + q.y*q.y + q.z*q.z + q.w*q.w;
    float k2 = k.x*k.x + k.y*k.y + k.z*k.z + k.w*k.w;
#pragma unroll
    for (int off = 16; off; off >>= 1) {
        q2 += __shfl_xor_sync(0xffffffffu, q2, off);
        k2 += __shfl_xor_sync(0xffffffffu, k2, off);
    }
    float qs = rsqrtf(q2 * (1.0f / HD) + 1e-6f);
    float ks = rsqrtf(k2 * (1.0f / HD) + 1e-6f);

    float4 qwv = *(const float4*)(qw + lane * 4);
    float4 kwv = *(const float4*)(kw + lane * 4);

    float qn0 = q.x * qs * qwv.x, qn1 = q.y * qs * qwv.y;
    float qn2 = q.z * qs * qwv.z, qn3 = q.w * qs * qwv.w;
    float kn0 = k.x * ks * kwv.x, kn1 = k.y * ks * kwv.y;
    float kn2 = k.z * ks * kwv.z, kn3 = k.w * ks * kwv.w;

    const float* rp = rot + (size_t)n * 256 + lane * 8;
    float4 rA = *(const float4*)rp;
    float4 rB = *(const float4*)(rp + 4);

    const float scale = 0.08838834764831845f * 1.4426950408889634f;
    float qo0 = (rA.x * qn0 + rA.y * qn1) * scale;
    float qo1 = (rA.z * qn0 + rA.w * qn1) * scale;
    float qo2 = (rB.x * qn2 + rB.y * qn3) * scale;
    float qo3 = (rB.z * qn2 + rB.w * qn3) * scale;
    float ko0 = rA.x * kn0 + rA.y * kn1;
    float ko1 = rA.z * kn0 + rA.w * kn1;
    float ko2 = rB.x * kn2 + rB.y * kn3;
    float ko3 = rB.z * kn2 + rB.w * kn3;

    uint2 qh = make_uint2(pack_f16(qo0, qo1), pack_f16(qo2, qo3));
    uint2 kh = make_uint2(pack_f16(ko0, ko1), pack_f16(ko2, ko3));
    *(uint2*)(g_Qf + base) = qh;
    *(uint2*)(g_Kf + base) = kh;
}

// ---------------------------------------------------------------------------
// Kernel 3: Flash attention, fp16 single-term. BM=128 (8 warps), D=128.
// 128-KEY stages (3-stage pipeline, 208896 B): one CP_WAIT + one barrier
// covers TWO 64-key compute subtiles. Q fragments register-resident.
// No-max exp2 softmax, deferred l reduction.
// ---------------------------------------------------------------------------
#define A_STR    272                 // smem row stride bytes (128 fp16 + pad)
#define A_KARR   (128*A_STR)         // 34816 (128-row K or V array)
#define A_STAGE  (2*A_KARR)          // K(128) + V(128) = 69632
#define ATT_SMEM (3*A_STAGE)         // 208896

__global__ __launch_bounds__(256, 1) void attn_mma_kernel(float* __restrict__ out)
{
    extern __shared__ char smem[];
    const unsigned sbase = smem_u32(smem);
    const int bh = blockIdx.y;
    const int q0 = blockIdx.x << 7;          // 128 rows per CTA
    const int tid = threadIdx.x;
    const int wid = tid >> 5, lane = tid & 31;
    const int l15 = lane & 15;
    const int gr = lane >> 2, qc = (lane & 3) * 2;

    // --- Load Q tile (128 rows fp16) into stage-0 region ---
    {
        const uint4* Qf4 = (const uint4*)g_Qf;
#pragma unroll
        for (int l = 0; l < 8; l++) {
            int t = tid + (l << 8);            // 0..2047
            int row = t >> 4, c = t & 15;
            size_t gi = (((size_t)bh * SEQ + q0 + row) * HD >> 3) + c;
            cp16(sbase + row * A_STR + c * 16, Qf4 + gi);
        }
    }
    CP_COMMIT();
    CP_WAIT(0);
    __syncthreads();

    // --- Hoist Q fragments to registers (once) ---
    unsigned qf[8][4];
    {
        int arow = wid * 16 + l15;
#pragma unroll
        for (int ks = 0; ks < 8; ks++) {
            int acol = ks * 16 + (lane >> 4) * 8;
            ldsm_x4(qf[ks], sbase + arow * A_STR + acol * 2);
        }
    }
    __syncthreads();   // staging free before K/V pipeline reuses it

    const uint4* Kf4 = (const uint4*)g_Kf;
    const uint4* Vf4 = (const uint4*)g_Vf;

    // stage = 128 keys: K rows 0..127 then V rows 0..127
    auto stage_load = [&](int st, int kt) {
        unsigned sb = sbase + st * A_STAGE;
#pragma unroll
        for (int l = 0; l < 16; l++) {
            int t = tid + (l << 8);            // 0..4095
            int arr = t >> 11;                 // 0: K, 1: V
            int w = t & 2047;
            int row = w >> 4, c = w & 15;      // row 0..127
            size_t gi = (((size_t)bh * SEQ + kt * 128 + row) * HD >> 3) + c;
            const uint4* s = arr ? Vf4 : Kf4;
            cp16(sb + arr * A_KARR + row * A_STR + c * 16, s + gi);
        }
    };

    float O[16][4];
#pragma unroll
    for (int n = 0; n < 16; n++)
#pragma unroll
        for (int e = 0; e < 4; e++) O[n][e] = 0.f;
    float l0 = 0.f, l1 = 0.f;

    const int NKT = SEQ / 128;   // 32
    stage_load(0, 0); CP_COMMIT();
    stage_load(1, 1); CP_COMMIT();

    int buf = 0;
    for (int kt = 0; kt < NKT; kt++) {
        CP_WAIT(1);
        __syncthreads();        // stage kt visible; all warps done with kt-1

        // Early prefetch into the buffer freed at kt-1.
        {
            int nb = buf + 2; if (nb >= 3) nb -= 3;
            if (kt + 2 < NKT) stage_load(nb, kt + 2);
            CP_COMMIT();
        }

        // Two 64-key subtiles from this stage, no barrier between them.
#pragma unroll
        for (int sub = 0; sub < 2; sub++) {
            unsigned sKf = sbase + buf * A_STAGE + sub * (64 * A_STR);
            unsigned sVf = sbase + buf * A_STAGE + A_KARR + sub * (64 * A_STR);

            // --- S = Q K^T (single term) ---
            float S[8][4];
#pragma unroll
            for (int j = 0; j < 8; j++)
#pragma unroll
                for (int e = 0; e < 4; e++) S[j][e] = 0.f;

            {
                int brow_off = (lane >> 4) * 8 + (lane & 7);
                int g_kh = ((lane >> 3) & 1) * 8;
#pragma unroll
                for (int ks = 0; ks < 8; ks++) {
                    int bcol = ks * 16 + g_kh;
#pragma unroll
                    for (int jj = 0; jj < 4; jj++) {
                        unsigned k4[4];
                        unsigned boff = (jj * 16 + brow_off) * A_STR
                                        + bcol * 2;
                        ldsm_x4(k4, sKf + boff);
                        mma16816(S[2*jj],   qf[ks], k4);
                        mma16816(S[2*jj+1], qf[ks], k4 + 2);
                    }
                }
            }

            // --- No-max softmax: P = exp2(S); accumulate partial l ---
#pragma unroll
            for (int j = 0; j < 8; j++) {
                S[j][0] = ex2(S[j][0]);
                S[j][1] = ex2(S[j][1]);
                S[j][2] = ex2(S[j][2]);
                S[j][3] = ex2(S[j][3]);
                l0 += S[j][0] + S[j][1];
                l1 += S[j][2] + S[j][3];
            }

            // --- O += P V (single term) ---
            {
                int vrow_off = (((lane >> 3) & 1) * 8) + (lane & 7);
                int vcol_off = (lane >> 4) * 16;
#pragma unroll
                for (int t = 0; t < 4; t++) {
                    unsigned ph[4];
                    const float* s0 = S[2 * t];
                    const float* s1 = S[2 * t + 1];
                    ph[0] = pack_f16(s0[0], s0[1]);
                    ph[1] = pack_f16(s0[2], s0[3]);
                    ph[2] = pack_f16(s1[0], s1[1]);
                    ph[3] = pack_f16(s1[2], s1[3]);
#pragma unroll
                    for (int nn = 0; nn < 8; nn += 2) {
                        unsigned vha[4], vhb[4];
                        unsigned va = (t * 16 + vrow_off) * A_STR
                                      + nn * 32 + vcol_off;
                        ldsm_x4_t(vha, sVf + va);
                        ldsm_x4_t(vhb, sVf + va + 32);
                        mma16816(O[2*nn],   ph, vha);
                        mma16816(O[2*nn+1], ph, vha + 2);
                        mma16816(O[2*nn+2], ph, vhb);
                        mma16816(O[2*nn+3], ph, vhb + 2);
                    }
                }
            }
        }

        if (++buf == 3) buf = 0;
    }

    // --- Final l reduction across the 4 lanes of each row group ---
    l0 += __shfl_xor_sync(0xffffffffu, l0, 1);
    l0 += __shfl_xor_sync(0xffffffffu, l0, 2);
    l1 += __shfl_xor_sync(0xffffffffu, l1, 1);
    l1 += __shfl_xor_sync(0xffffffffu, l1, 2);

    // --- Write output ---
    const int b = bh >> 4, h = bh & 15;
    float inv0 = __fdividef(1.0f, l0);
    float inv1 = __fdividef(1.0f, l1);
    int n0g = q0 + wid * 16 + gr;
    float* o0 = out + ((size_t)b * SEQ + n0g) * DIM + h * HD;
    float* o1 = out + ((size_t)b * SEQ + n0g + 8) * DIM + h * HD;
#pragma unroll
    for (int n = 0; n < 16; n++) {
        int d = n * 8 + qc;
        float2 w0 = make_float2(O[n][0] * inv0, O[n][1] * inv0);
        float2 w1 = make_float2(O[n][2] * inv1, O[n][3] * inv1);
        *(float2*)(o0 + d) = w0;
        *(float2*)(o1 + d) = w1;
    }
}

// ---------------------------------------------------------------------------
extern "C" void kernel_launch(void* const* d_in, const int* in_sizes, int n_in,
                              void* d_out, int out_size)
{
    const float* x    = (const float*)d_in[0];
    const float* rot  = (const float*)d_in[1];
    const float* W    = (const float*)d_in[2];
    const float* bias = (const float*)d_in[3];
    const float* qw   = (const float*)d_in[4];
    const float* kw   = (const float*)d_in[5];
    float* out = (float*)d_out;

    convert_x_kernel<<<(MROWS * DIM) / (256 * 8), 256>>>(x);
    convert_w_kernel<<<dim3(QKV_COLS / 32, DIM / 32), dim3(32, 8)>>>(W);

    cudaFuncSetAttribute(qkv_gemm_mma_kernel,
                         cudaFuncAttributeMaxDynamicSharedMemorySize, GEMM_SMEM);
    qkv_gemm_mma_kernel<<<dim3(QKV_COLS / 256, MROWS / 128), 256, GEMM_SMEM>>>(bias);

    norm_rope_kernel<<<(BATCH * NHEADS * SEQ) / 8, 256>>>(rot, qw, kw);

    cudaFuncSetAttribute(attn_mma_kernel,
                         cudaFuncAttributeMaxDynamicSharedMemorySize, ATT_SMEM);
    attn_mma_kernel<<<dim3(SEQ / 128, BATCH * NHEADS), 256, ATT_SMEM>>>(out);
}

// round 12
// speedup vs baseline: 2.5475x; 1.1108x over previous
#include <cuda_runtime.h>
#include <cuda_fp16.h>
#include <math_constants.h>

#define DIM     2048
#define NHEADS  16
#define HD      128
#define BATCH   2
#define SEQ     4096
#define QKV_COLS (3*DIM)        // 6144
#define MROWS   (BATCH*SEQ)     // 8192

// ---------------------------------------------------------------------------
// Device-global scratch
// ---------------------------------------------------------------------------
__device__ float g_Q[(size_t)BATCH*NHEADS*SEQ*HD];   // pre-norm Q (fp32)
__device__ float g_K[(size_t)BATCH*NHEADS*SEQ*HD];   // pre-norm K (fp32)
__device__ __half g_Qf[(size_t)BATCH*NHEADS*SEQ*HD]; // normed+rope, scaled
__device__ __half g_Kf[(size_t)BATCH*NHEADS*SEQ*HD];
__device__ __half g_Vf[(size_t)BATCH*NHEADS*SEQ*HD];
__device__ __half g_xh[(size_t)MROWS*DIM];           // x (fp16)
__device__ __half g_wt[(size_t)QKV_COLS*DIM];        // W^T (fp16)

// ---------------------------------------------------------------------------
// PTX helpers (arch-neutral: mma.sync / ldmatrix / cp.async, sm_80+)
// ---------------------------------------------------------------------------
__device__ __forceinline__ unsigned smem_u32(const void* p) {
    unsigned a;
    asm("{ .reg .u64 t; cvta.to.shared.u64 t, %1; cvt.u32.u64 %0, t; }"
        : "=r"(a) : "l"(p));
    return a;
}
__device__ __forceinline__ void ldsm_x4(unsigned r[4], unsigned a) {
    asm volatile("ldmatrix.sync.aligned.m8n8.x4.shared.b16 {%0,%1,%2,%3}, [%4];"
                 : "=r"(r[0]), "=r"(r[1]), "=r"(r[2]), "=r"(r[3]) : "r"(a));
}
__device__ __forceinline__ void ldsm_x4_t(unsigned r[4], unsigned a) {
    asm volatile("ldmatrix.sync.aligned.m8n8.x4.trans.shared.b16 {%0,%1,%2,%3}, [%4];"
                 : "=r"(r[0]), "=r"(r[1]), "=r"(r[2]), "=r"(r[3]) : "r"(a));
}
__device__ __forceinline__ void mma16816(float c[4], const unsigned a[4],
                                         const unsigned b[2]) {
    asm volatile(
        "mma.sync.aligned.m16n8k16.row.col.f32.f16.f16.f32 "
        "{%0,%1,%2,%3}, {%4,%5,%6,%7}, {%8,%9}, {%0,%1,%2,%3};"
        : "+f"(c[0]), "+f"(c[1]), "+f"(c[2]), "+f"(c[3])
        : "r"(a[0]), "r"(a[1]), "r"(a[2]), "r"(a[3]), "r"(b[0]), "r"(b[1]));
}
__device__ __forceinline__ unsigned pack_f16(float lo, float hi) {
    unsigned r;
    asm("cvt.rn.f16x2.f32 %0, %1, %2;" : "=r"(r) : "f"(hi), "f"(lo));
    return r;
}
__device__ __forceinline__ float ex2(float x) {
    float y;
    asm("ex2.approx.f32 %0, %1;" : "=f"(y) : "f"(x));
    return y;
}
__device__ __forceinline__ void cp16(unsigned dst, const void* src) {
    asm volatile("cp.async.cg.shared.global [%0], [%1], 16;"
                 :: "r"(dst), "l"(src));
}
#define CP_COMMIT()  asm volatile("cp.async.commit_group;" ::: "memory")
#define CP_WAIT(n)   asm volatile("cp.async.wait_group %0;" :: "n"(n) : "memory")

// ---------------------------------------------------------------------------
// Kernel 0a: convert x (fp32) to fp16
// ---------------------------------------------------------------------------
__global__ void convert_x_kernel(const float* __restrict__ x)
{
    size_t i = ((size_t)blockIdx.x * 256 + threadIdx.x) * 8;
    float4 v0 = *(const float4*)(x + i);
    float4 v1 = *(const float4*)(x + i + 4);
    uint4 o;
    o.x = pack_f16(v0.x, v0.y);
    o.y = pack_f16(v0.z, v0.w);
    o.z = pack_f16(v1.x, v1.y);
    o.w = pack_f16(v1.z, v1.w);
    *(uint4*)(g_xh + i) = o;
}

// ---------------------------------------------------------------------------
// Kernel 0b: transpose W [k][n] -> [n][k], fp16
// ---------------------------------------------------------------------------
__global__ void convert_w_kernel(const float* __restrict__ W)
{
    __shared__ float tile[32][33];
    int tx = threadIdx.x, ty = threadIdx.y;          // block (32, 8)
    int n0 = blockIdx.x * 32, k0 = blockIdx.y * 32;
#pragma unroll
    for (int r = 0; r < 4; r++) {
        int k = k0 + ty + r * 8;
        tile[ty + r * 8][tx] = W[(size_t)k * QKV_COLS + n0 + tx];
    }
    __syncthreads();
#pragma unroll
    for (int r = 0; r < 4; r++) {
        int n = n0 + ty + r * 8;
        int k = k0 + tx;
        g_wt[(size_t)n * DIM + k] = __float2half(tile[tx][ty + r * 8]);
    }
}

// ---------------------------------------------------------------------------
// Kernel 1: QKV GEMM, single-term fp16. CTA 128x256, K-chunk 64,
// 4-stage cp.async pipeline, ONE barrier per iteration. 8 warps.
// Epilogue: stage acc tile in smem, re-read sorted by (j,h,d) so global
// stores are fully coalesced (the naive de-interleave scatter cost ~1.6 GB
// of 32B-sector write traffic).
// ---------------------------------------------------------------------------
#define G_STR    144                // smem row stride bytes (64 fp16 + 16B pad)
#define G_A_ARR  (128*G_STR)        // 18432
#define G_B_ARR  (256*G_STR)        // 36864
#define G_STAGE  (G_A_ARR + G_B_ARR)       // 55296
#define GEMM_SMEM (4*G_STAGE)       // 221184
#define E_STR    260                // epilogue smem stride (floats)

__global__ __launch_bounds__(256, 1) void qkv_gemm_mma_kernel(
    const float* __restrict__ bias)
{
    extern __shared__ char smem[];
    const unsigned sbase = smem_u32(smem);
    const int tid = threadIdx.x;
    const int wid = tid >> 5, lane = tid & 31;
    const int warp_m = wid >> 1, warp_n = wid & 1;
    const int gM0 = blockIdx.y << 7;
    const int gN0 = blockIdx.x << 8;
    const int l15 = lane & 15;

    float acc[2][16][4];
#pragma unroll
    for (int i = 0; i < 2; i++)
#pragma unroll
        for (int j = 0; j < 16; j++)
#pragma unroll
            for (int e = 0; e < 4; e++) acc[i][j][e] = 0.f;

    const uint4* xh4 = (const uint4*)g_xh;
    const uint4* wt4 = (const uint4*)g_wt;

    auto stage_load = [&](int st, int it) {
        unsigned sb = sbase + st * G_STAGE;
        int k0 = it * 64;
#pragma unroll
        for (int l = 0; l < 12; l++) {
            int t = tid + (l << 8);                // 0..3071
            if (t < 1024) {                        // A
                int row = t >> 3, c4 = t & 7;
                size_t gi = (((size_t)(gM0 + row) * DIM + k0) >> 3) + c4;
                cp16(sb + row * G_STR + c4 * 16, xh4 + gi);
            } else {                               // B
                int w = t - 1024;
                int row = w >> 3, c4 = w & 7;
                size_t gi = (((size_t)(gN0 + row) * DIM + k0) >> 3) + c4;
                cp16(sb + G_A_ARR + row * G_STR + c4 * 16, wt4 + gi);
            }
        }
    };

    const int NIT = DIM / 64;        // 32
    stage_load(0, 0); CP_COMMIT();
    stage_load(1, 1); CP_COMMIT();
    stage_load(2, 2); CP_COMMIT();

    int buf = 0;
    for (int it = 0; it < NIT; ++it) {
        CP_WAIT(2);
        __syncthreads();     // stage it visible; all warps finished it-1

        // Early prefetch: buffer (buf+3)&3 held it-1, freed by the barrier.
        {
            int nb = (buf + 3) & 3;
            if (it + 3 < NIT) stage_load(nb, it + 3);
            CP_COMMIT();
        }

        unsigned sb = sbase + buf * G_STAGE;
        unsigned sA = sb, sB = sb + G_A_ARR;

#pragma unroll
        for (int ks = 0; ks < 4; ks++) {
            unsigned a4[2][4];
            int acol = ks * 16 + (lane >> 4) * 8;
#pragma unroll
            for (int i = 0; i < 2; i++) {
                int arow = warp_m * 32 + i * 16 + l15;
                ldsm_x4(a4[i], sA + arow * G_STR + acol * 2);
            }
            int brow_off = (lane >> 4) * 8 + (lane & 7);
            int bcol = ks * 16 + ((lane >> 3) & 1) * 8;
#pragma unroll
            for (int jj = 0; jj < 8; jj++) {
                unsigned b4[4];
                unsigned boff = (warp_n * 128 + jj * 16 + brow_off) * G_STR
                                + bcol * 2;
                ldsm_x4(b4, sB + boff);
                mma16816(acc[0][2*jj],   a4[0], b4);
                mma16816(acc[0][2*jj+1], a4[0], b4 + 2);
                mma16816(acc[1][2*jj],   a4[1], b4);
                mma16816(acc[1][2*jj+1], a4[1], b4 + 2);
            }
        }
        buf = (buf + 1) & 3;
    }

    // -------- Epilogue: smem-staged, coalesced de-interleave --------
    CP_WAIT(0);
    __syncthreads();               // pipeline fully drained, smem reusable

    float* sE = (float*)smem;      // 128 x 256 tile, stride E_STR floats
    const int gr = lane >> 2, qc = (lane & 3) * 2;
#pragma unroll
    for (int i = 0; i < 2; i++) {
#pragma unroll
        for (int j = 0; j < 16; j++) {
#pragma unroll
            for (int half = 0; half < 2; half++) {
                int row = warp_m * 32 + i * 16 + half * 8 + gr;
                int col = warp_n * 128 + j * 8 + qc;
                sE[row * E_STR + col]     = acc[i][j][half * 2];
                sE[row * E_STR + col + 1] = acc[i][j][half * 2 + 1];
            }
        }
    }
    __syncthreads();

    // thread tid -> (j, c) sorted by (j, c ascending)
    const int m = gN0 % 3;
    const int cnt0 = 85 + (m == 0 ? 1 : 0);
    const int cnt1 = 85 + (m == 1 ? 1 : 0);
    int jsel, idx;
    if (tid < cnt0)             { jsel = 0; idx = tid; }
    else if (tid < cnt0 + cnt1) { jsel = 1; idx = tid - cnt0; }
    else                        { jsel = 2; idx = tid - cnt0 - cnt1; }
    int c = gN0 + (((jsel - m) % 3) + 3) % 3 + 3 * idx;   // global col
    int cl = c - gN0;
    int h = c / 384;
    int d = (c - h * 384) / 3;                            // rem%3==jsel
    float bias_c = __ldg(bias + c);

    const int b = gM0 >> 12;
    const int n0 = gM0 & (SEQ - 1);
    size_t base = (((size_t)(b * NHEADS + h)) * SEQ + n0) * HD + d;

    if (jsel == 0) {
        float* p = g_Q + base;
#pragma unroll 4
        for (int r = 0; r < 128; r++)
            p[(size_t)r * HD] = sE[r * E_STR + cl] + bias_c;
    } else if (jsel == 1) {
        float* p = g_K + base;
#pragma unroll 4
        for (int r = 0; r < 128; r++)
            p[(size_t)r * HD] = sE[r * E_STR + cl] + bias_c;
    } else {
        __half* p = g_Vf + base;
#pragma unroll 4
        for (int r = 0; r < 128; r++)
            p[(size_t)r * HD] = __float2half(sE[r * E_STR + cl] + bias_c);
    }
}

// ---------------------------------------------------------------------------
// Kernel 2: RMSNorm + RoPE, warp-per-row. Outputs fp16 Q (scaled by
// (1/sqrt(HD))*log2(e)) and fp16 K.
// ---------------------------------------------------------------------------
__global__ __launch_bounds__(256) void norm_rope_kernel(
    const float* __restrict__ rot, const float* __restrict__ qw,
    const float* __restrict__ kw)
{
    const int lane = threadIdx.x & 31;
    const int row = blockIdx.x * 8 + (threadIdx.x >> 5);
    const int n = row & (SEQ - 1);
    const size_t base = (size_t)row * HD + lane * 4;

    float4 q = *(const float4*)(g_Q + base);
    float4 k = *(const float4*)(g_K + base);

    float q2 = q.x*q.x + q.y*q.y + q.z*q.z + q.w*q.w;
    float k2 = k.x*k.x + k.y*k.y + k.z*k.z + k.w*k.w;
#pragma unroll
    for (int off = 16; off; off >>= 1) {
        q2 += __shfl_xor_sync(0xffffffffu, q2, off);
        k2 += __shfl_xor_sync(0xffffffffu, k2, off);
    }
    float qs = rsqrtf(q2 * (1.0f / HD) + 1e-6f);
    float ks = rsqrtf(k2 * (1.0f / HD) + 1e-6f);

    float4 qwv = *(const float4*)(qw + lane * 4);
    float4 kwv = *(const float4*)(kw + lane * 4);

    float qn0 = q.x * qs * qwv.x, qn1 = q.y * qs * qwv.y;
    float qn2 = q.z * qs * qwv.z, qn3 = q.w * qs * qwv.w;
    float kn0 = k.x * ks * kwv.x, kn1 = k.y * ks * kwv.y;
    float kn2 = k.z * ks * kwv.z, kn3 = k.w * ks * kwv.w;

    const float* rp = rot + (size_t)n * 256 + lane * 8;
    float4 rA = *(const float4*)rp;
    float4 rB = *(const float4*)(rp + 4);

    const float scale = 0.08838834764831845f * 1.4426950408889634f;
    float qo0 = (rA.x * qn0 + rA.y * qn1) * scale;
    float qo1 = (rA.z * qn0 + rA.w * qn1) * scale;
    float qo2 = (rB.x * qn2 + rB.y * qn3) * scale;
    float qo3 = (rB.z * qn2 + rB.w * qn3) * scale;
    float ko0 = rA.x * kn0 + rA.y * kn1;
    float ko1 = rA.z * kn0 + rA.w * kn1;
    float ko2 = rB.x * kn2 + rB.y * kn3;
    float ko3 = rB.z * kn2 + rB.w * kn3;

    uint2 qh = make_uint2(pack_f16(qo0, qo1), pack_f16(qo2, qo3));
    uint2 kh = make_uint2(pack_f16(ko0, ko1), pack_f16(ko2, ko3));
    *(uint2*)(g_Qf + base) = qh;
    *(uint2*)(g_Kf + base) = kh;
}

// ---------------------------------------------------------------------------
// Kernel 3: Flash attention, fp16 single-term. BM=128 (8 warps), D=128.
// 128-key stages (3-stage pipeline): one CP_WAIT + one barrier covers two
// 64-key compute subtiles. Q fragments register-resident. No-max exp2
// softmax, deferred l reduction.
// ---------------------------------------------------------------------------
#define A_STR    272                 // smem row stride bytes (128 fp16 + pad)
#define A_KARR   (128*A_STR)         // 34816 (128-row K or V array)
#define A_STAGE  (2*A_KARR)          // K(128) + V(128) = 69632
#define ATT_SMEM (3*A_STAGE)         // 208896

__global__ __launch_bounds__(256, 1) void attn_mma_kernel(float* __restrict__ out)
{
    extern __shared__ char smem[];
    const unsigned sbase = smem_u32(smem);
    const int bh = blockIdx.y;
    const int q0 = blockIdx.x << 7;          // 128 rows per CTA
    const int tid = threadIdx.x;
    const int wid = tid >> 5, lane = tid & 31;
    const int l15 = lane & 15;
    const int gr = lane >> 2, qc = (lane & 3) * 2;

    // --- Load Q tile (128 rows fp16) into stage-0 region ---
    {
        const uint4* Qf4 = (const uint4*)g_Qf;
#pragma unroll
        for (int l = 0; l < 8; l++) {
            int t = tid + (l << 8);            // 0..2047
            int row = t >> 4, c = t & 15;
            size_t gi = (((size_t)bh * SEQ + q0 + row) * HD >> 3) + c;
            cp16(sbase + row * A_STR + c * 16, Qf4 + gi);
        }
    }
    CP_COMMIT();
    CP_WAIT(0);
    __syncthreads();

    // --- Hoist Q fragments to registers (once) ---
    unsigned qf[8][4];
    {
        int arow = wid * 16 + l15;
#pragma unroll
        for (int ks = 0; ks < 8; ks++) {
            int acol = ks * 16 + (lane >> 4) * 8;
            ldsm_x4(qf[ks], sbase + arow * A_STR + acol * 2);
        }
    }
    __syncthreads();   // staging free before K/V pipeline reuses it

    const uint4* Kf4 = (const uint4*)g_Kf;
    const uint4* Vf4 = (const uint4*)g_Vf;

    // stage = 128 keys: K rows 0..127 then V rows 0..127
    auto stage_load = [&](int st, int kt) {
        unsigned sb = sbase + st * A_STAGE;
#pragma unroll
        for (int l = 0; l < 16; l++) {
            int t = tid + (l << 8);            // 0..4095
            int arr = t >> 11;                 // 0: K, 1: V
            int w = t & 2047;
            int row = w >> 4, c = w & 15;      // row 0..127
            size_t gi = (((size_t)bh * SEQ + kt * 128 + row) * HD >> 3) + c;
            const uint4* s = arr ? Vf4 : Kf4;
            cp16(sb + arr * A_KARR + row * A_STR + c * 16, s + gi);
        }
    };

    float O[16][4];
#pragma unroll
    for (int n = 0; n < 16; n++)
#pragma unroll
        for (int e = 0; e < 4; e++) O[n][e] = 0.f;
    float l0 = 0.f, l1 = 0.f;

    const int NKT = SEQ / 128;   // 32
    stage_load(0, 0); CP_COMMIT();
    stage_load(1, 1); CP_COMMIT();

    int buf = 0;
    for (int kt = 0; kt < NKT; kt++) {
        CP_WAIT(1);
        __syncthreads();        // stage kt visible; all warps done with kt-1

        // Early prefetch into the buffer freed at kt-1.
        {
            int nb = buf + 2; if (nb >= 3) nb -= 3;
            if (kt + 2 < NKT) stage_load(nb, kt + 2);
            CP_COMMIT();
        }

        // Two 64-key subtiles from this stage, no barrier between them.
#pragma unroll
        for (int sub = 0; sub < 2; sub++) {
            unsigned sKf = sbase + buf * A_STAGE + sub * (64 * A_STR);
            unsigned sVf = sbase + buf * A_STAGE + A_KARR + sub * (64 * A_STR);

            // --- S = Q K^T (single term) ---
            float S[8][4];
#pragma unroll
            for (int j = 0; j < 8; j++)
#pragma unroll
                for (int e = 0; e < 4; e++) S[j][e] = 0.f;

            {
                int brow_off = (lane >> 4) * 8 + (lane & 7);
                int g_kh = ((lane >> 3) & 1) * 8;
#pragma unroll
                for (int ks = 0; ks < 8; ks++) {
                    int bcol = ks * 16 + g_kh;
#pragma unroll
                    for (int jj = 0; jj < 4; jj++) {
                        unsigned k4[4];
                        unsigned boff = (jj * 16 + brow_off) * A_STR
                                        + bcol * 2;
                        ldsm_x4(k4, sKf + boff);
                        mma16816(S[2*jj],   qf[ks], k4);
                        mma16816(S[2*jj+1], qf[ks], k4 + 2);
                    }
                }
            }

            // --- No-max softmax: P = exp2(S); accumulate partial l ---
#pragma unroll
            for (int j = 0; j < 8; j++) {
                S[j][0] = ex2(S[j][0]);
                S[j][1] = ex2(S[j][1]);
                S[j][2] = ex2(S[j][2]);
                S[j][3] = ex2(S[j][3]);
                l0 += S[j][0] + S[j][1];
                l1 += S[j][2] + S[j][3];
            }

            // --- O += P V (single term) ---
            {
                int vrow_off = (((lane >> 3) & 1) * 8) + (lane & 7);
                int vcol_off = (lane >> 4) * 16;
#pragma unroll
                for (int t = 0; t < 4; t++) {
                    unsigned ph[4];
                    const float* s0 = S[2 * t];
                    const float* s1 = S[2 * t + 1];
                    ph[0] = pack_f16(s0[0], s0[1]);
                    ph[1] = pack_f16(s0[2], s0[3]);
                    ph[2] = pack_f16(s1[0], s1[1]);
                    ph[3] = pack_f16(s1[2], s1[3]);
#pragma unroll
                    for (int nn = 0; nn < 8; nn += 2) {
                        unsigned vha[4], vhb[4];
                        unsigned va = (t * 16 + vrow_off) * A_STR
                                      + nn * 32 + vcol_off;
                        ldsm_x4_t(vha, sVf + va);
                        ldsm_x4_t(vhb, sVf + va + 32);
                        mma16816(O[2*nn],   ph, vha);
                        mma16816(O[2*nn+1], ph, vha + 2);
                        mma16816(O[2*nn+2], ph, vhb);
                        mma16816(O[2*nn+3], ph, vhb + 2);
                    }
                }
            }
        }

        if (++buf == 3) buf = 0;
    }

    // --- Final l reduction across the 4 lanes of each row group ---
    l0 += __shfl_xor_sync(0xffffffffu, l0, 1);
    l0 += __shfl_xor_sync(0xffffffffu, l0, 2);
    l1 += __shfl_xor_sync(0xffffffffu, l1, 1);
    l1 += __shfl_xor_sync(0xffffffffu, l1, 2);

    // --- Write output ---
    const int b = bh >> 4, h = bh & 15;
    float inv0 = __fdividef(1.0f, l0);
    float inv1 = __fdividef(1.0f, l1);
    int n0g = q0 + wid * 16 + gr;
    float* o0 = out + ((size_t)b * SEQ + n0g) * DIM + h * HD;
    float* o1 = out + ((size_t)b * SEQ + n0g + 8) * DIM + h * HD;
#pragma unroll
    for (int n = 0; n < 16; n++) {
        int d = n * 8 + qc;
        float2 w0 = make_float2(O[n][0] * inv0, O[n][1] * inv0);
        float2 w1 = make_float2(O[n][2] * inv1, O[n][3] * inv1);
        *(float2*)(o0 + d) = w0;
        *(float2*)(o1 + d) = w1;
    }
}

// ---------------------------------------------------------------------------
extern "C" void kernel_launch(void* const* d_in, const int* in_sizes, int n_in,
                              void* d_out, int out_size)
{
    const float* x    = (const float*)d_in[0];
    const float* rot  = (const float*)d_in[1];
    const float* W    = (const float*)d_in[2];
    const float* bias = (const float*)d_in[3];
    const float* qw   = (const float*)d_in[4];
    const float* kw   = (const float*)d_in[5];
    float* out = (float*)d_out;

    convert_x_kernel<<<(MROWS * DIM) / (256 * 8), 256>>>(x);
    convert_w_kernel<<<dim3(QKV_COLS / 32, DIM / 32), dim3(32, 8)>>>(W);

    cudaFuncSetAttribute(qkv_gemm_mma_kernel,
                         cudaFuncAttributeMaxDynamicSharedMemorySize, GEMM_SMEM);
    qkv_gemm_mma_kernel<<<dim3(QKV_COLS / 256, MROWS / 128), 256, GEMM_SMEM>>>(bias);

    norm_rope_kernel<<<(BATCH * NHEADS * SEQ) / 8, 256>>>(rot, qw, kw);

    cudaFuncSetAttribute(attn_mma_kernel,
                         cudaFuncAttributeMaxDynamicSharedMemorySize, ATT_SMEM);
    attn_mma_kernel<<<dim3(SEQ / 128, BATCH * NHEADS), 256, ATT_SMEM>>>(out);
}

// round 13
// speedup vs baseline: 2.6604x; 1.0443x over previous
#include <cuda_runtime.h>
#include <cuda_fp16.h>
#include <math_constants.h>

#define DIM     2048
#define NHEADS  16
#define HD      128
#define BATCH   2
#define SEQ     4096
#define QKV_COLS (3*DIM)        // 6144
#define MROWS   (BATCH*SEQ)     // 8192

// ---------------------------------------------------------------------------
// Device-global scratch
// ---------------------------------------------------------------------------
__device__ __half g_Qp[(size_t)BATCH*NHEADS*SEQ*HD]; // pre-norm Q (fp16)
__device__ __half g_Kp[(size_t)BATCH*NHEADS*SEQ*HD]; // pre-norm K (fp16)
__device__ __half g_Qf[(size_t)BATCH*NHEADS*SEQ*HD]; // normed+rope, scaled
__device__ __half g_Kf[(size_t)BATCH*NHEADS*SEQ*HD];
__device__ __half g_Vf[(size_t)BATCH*NHEADS*SEQ*HD];
__device__ __half g_xh[(size_t)MROWS*DIM];           // x (fp16)
__device__ __half g_wt[(size_t)QKV_COLS*DIM];        // W^T (fp16)

// ---------------------------------------------------------------------------
// PTX helpers (arch-neutral: mma.sync / ldmatrix / cp.async, sm_80+)
// ---------------------------------------------------------------------------
__device__ __forceinline__ unsigned smem_u32(const void* p) {
    unsigned a;
    asm("{ .reg .u64 t; cvta.to.shared.u64 t, %1; cvt.u32.u64 %0, t; }"
        : "=r"(a) : "l"(p));
    return a;
}
__device__ __forceinline__ void ldsm_x4(unsigned r[4], unsigned a) {
    asm volatile("ldmatrix.sync.aligned.m8n8.x4.shared.b16 {%0,%1,%2,%3}, [%4];"
                 : "=r"(r[0]), "=r"(r[1]), "=r"(r[2]), "=r"(r[3]) : "r"(a));
}
__device__ __forceinline__ void ldsm_x4_t(unsigned r[4], unsigned a) {
    asm volatile("ldmatrix.sync.aligned.m8n8.x4.trans.shared.b16 {%0,%1,%2,%3}, [%4];"
                 : "=r"(r[0]), "=r"(r[1]), "=r"(r[2]), "=r"(r[3]) : "r"(a));
}
__device__ __forceinline__ void mma16816(float c[4], const unsigned a[4],
                                         const unsigned b[2]) {
    asm volatile(
        "mma.sync.aligned.m16n8k16.row.col.f32.f16.f16.f32 "
        "{%0,%1,%2,%3}, {%4,%5,%6,%7}, {%8,%9}, {%0,%1,%2,%3};"
        : "+f"(c[0]), "+f"(c[1]), "+f"(c[2]), "+f"(c[3])
        : "r"(a[0]), "r"(a[1]), "r"(a[2]), "r"(a[3]), "r"(b[0]), "r"(b[1]));
}
__device__ __forceinline__ unsigned pack_f16(float lo, float hi) {
    unsigned r;
    asm("cvt.rn.f16x2.f32 %0, %1, %2;" : "=r"(r) : "f"(hi), "f"(lo));
    return r;
}
__device__ __forceinline__ float ex2(float x) {
    float y;
    asm("ex2.approx.f32 %0, %1;" : "=f"(y) : "f"(x));
    return y;
}
__device__ __forceinline__ void cp16(unsigned dst, const void* src) {
    asm volatile("cp.async.cg.shared.global [%0], [%1], 16;"
                 :: "r"(dst), "l"(src));
}
#define CP_COMMIT()  asm volatile("cp.async.commit_group;" ::: "memory")
#define CP_WAIT(n)   asm volatile("cp.async.wait_group %0;" :: "n"(n) : "memory")

// ---------------------------------------------------------------------------
// Kernel 0a: convert x (fp32) to fp16
// ---------------------------------------------------------------------------
__global__ void convert_x_kernel(const float* __restrict__ x)
{
    size_t i = ((size_t)blockIdx.x * 256 + threadIdx.x) * 8;
    float4 v0 = *(const float4*)(x + i);
    float4 v1 = *(const float4*)(x + i + 4);
    uint4 o;
    o.x = pack_f16(v0.x, v0.y);
    o.y = pack_f16(v0.z, v0.w);
    o.z = pack_f16(v1.x, v1.y);
    o.w = pack_f16(v1.z, v1.w);
    *(uint4*)(g_xh + i) = o;
}

// ---------------------------------------------------------------------------
// Kernel 0b: transpose W [k][n] -> [n][k], fp16
// ---------------------------------------------------------------------------
__global__ void convert_w_kernel(const float* __restrict__ W)
{
    __shared__ float tile[32][33];
    int tx = threadIdx.x, ty = threadIdx.y;          // block (32, 8)
    int n0 = blockIdx.x * 32, k0 = blockIdx.y * 32;
#pragma unroll
    for (int r = 0; r < 4; r++) {
        int k = k0 + ty + r * 8;
        tile[ty + r * 8][tx] = W[(size_t)k * QKV_COLS + n0 + tx];
    }
    __syncthreads();
#pragma unroll
    for (int r = 0; r < 4; r++) {
        int n = n0 + ty + r * 8;
        int k = k0 + tx;
        g_wt[(size_t)n * DIM + k] = __float2half(tile[tx][ty + r * 8]);
    }
}

// ---------------------------------------------------------------------------
// Kernel 1: QKV GEMM, single-term fp16. CTA 128x256, K-chunk 64,
// 4-stage cp.async pipeline, ONE barrier per iteration. 8 warps in a
// 2(M)x4(N) grid, warp tile 64x64 (32 LDSM/iter instead of 40).
// Epilogue: smem-staged coalesced de-interleave; all outputs fp16.
// ---------------------------------------------------------------------------
#define G_STR    144                // smem row stride bytes (64 fp16 + 16B pad)
#define G_A_ARR  (128*G_STR)        // 18432
#define G_B_ARR  (256*G_STR)        // 36864
#define G_STAGE  (G_A_ARR + G_B_ARR)       // 55296
#define GEMM_SMEM (4*G_STAGE)       // 221184
#define E_STR    260                // epilogue smem stride (floats)

__global__ __launch_bounds__(256, 1) void qkv_gemm_mma_kernel(
    const float* __restrict__ bias)
{
    extern __shared__ char smem[];
    const unsigned sbase = smem_u32(smem);
    const int tid = threadIdx.x;
    const int wid = tid >> 5, lane = tid & 31;
    const int warp_m = wid >> 2;            // 0..1 (64 rows each)
    const int warp_n = wid & 3;             // 0..3 (64 cols each)
    const int gM0 = blockIdx.y << 7;
    const int gN0 = blockIdx.x << 8;
    const int l15 = lane & 15;

    float acc[4][8][4];
#pragma unroll
    for (int i = 0; i < 4; i++)
#pragma unroll
        for (int j = 0; j < 8; j++)
#pragma unroll
            for (int e = 0; e < 4; e++) acc[i][j][e] = 0.f;

    const uint4* xh4 = (const uint4*)g_xh;
    const uint4* wt4 = (const uint4*)g_wt;

    auto stage_load = [&](int st, int it) {
        unsigned sb = sbase + st * G_STAGE;
        int k0 = it * 64;
#pragma unroll
        for (int l = 0; l < 12; l++) {
            int t = tid + (l << 8);                // 0..3071
            if (t < 1024) {                        // A
                int row = t >> 3, c4 = t & 7;
                size_t gi = (((size_t)(gM0 + row) * DIM + k0) >> 3) + c4;
                cp16(sb + row * G_STR + c4 * 16, xh4 + gi);
            } else {                               // B
                int w = t - 1024;
                int row = w >> 3, c4 = w & 7;
                size_t gi = (((size_t)(gN0 + row) * DIM + k0) >> 3) + c4;
                cp16(sb + G_A_ARR + row * G_STR + c4 * 16, wt4 + gi);
            }
        }
    };

    const int NIT = DIM / 64;        // 32
    stage_load(0, 0); CP_COMMIT();
    stage_load(1, 1); CP_COMMIT();
    stage_load(2, 2); CP_COMMIT();

    int buf = 0;
    for (int it = 0; it < NIT; ++it) {
        CP_WAIT(2);
        __syncthreads();     // stage it visible; all warps finished it-1

        // Early prefetch: buffer (buf+3)&3 held it-1, freed by the barrier.
        {
            int nb = (buf + 3) & 3;
            if (it + 3 < NIT) stage_load(nb, it + 3);
            CP_COMMIT();
        }

        unsigned sb = sbase + buf * G_STAGE;
        unsigned sA = sb, sB = sb + G_A_ARR;

#pragma unroll
        for (int ks = 0; ks < 4; ks++) {
            unsigned a4[4][4], b4[4][4];
            int acol = ks * 16 + (lane >> 4) * 8;
#pragma unroll
            for (int i = 0; i < 4; i++) {
                int arow = warp_m * 64 + i * 16 + l15;
                ldsm_x4(a4[i], sA + arow * G_STR + acol * 2);
            }
            int brow_off = (lane >> 4) * 8 + (lane & 7);
            int bcol = ks * 16 + ((lane >> 3) & 1) * 8;
#pragma unroll
            for (int jj = 0; jj < 4; jj++) {
                unsigned boff = (warp_n * 64 + jj * 16 + brow_off) * G_STR
                                + bcol * 2;
                ldsm_x4(b4[jj], sB + boff);
            }
#pragma unroll
            for (int i = 0; i < 4; i++)
#pragma unroll
                for (int jj = 0; jj < 4; jj++) {
                    mma16816(acc[i][2*jj],   a4[i], b4[jj]);
                    mma16816(acc[i][2*jj+1], a4[i], b4[jj] + 2);
                }
        }
        buf = (buf + 1) & 3;
    }

    // -------- Epilogue: smem-staged, coalesced de-interleave --------
    CP_WAIT(0);
    __syncthreads();               // pipeline fully drained, smem reusable

    float* sE = (float*)smem;      // 128 x 256 tile, stride E_STR floats
    const int gr = lane >> 2, qc = (lane & 3) * 2;
#pragma unroll
    for (int i = 0; i < 4; i++) {
#pragma unroll
        for (int j = 0; j < 8; j++) {
#pragma unroll
            for (int half = 0; half < 2; half++) {
                int row = warp_m * 64 + i * 16 + half * 8 + gr;
                int col = warp_n * 64 + j * 8 + qc;
                sE[row * E_STR + col]     = acc[i][j][half * 2];
                sE[row * E_STR + col + 1] = acc[i][j][half * 2 + 1];
            }
        }
    }
    __syncthreads();

    // thread tid -> (j, c) sorted by (j, c ascending)
    const int m = gN0 % 3;
    const int cnt0 = 85 + (m == 0 ? 1 : 0);
    const int cnt1 = 85 + (m == 1 ? 1 : 0);
    int jsel, idx;
    if (tid < cnt0)             { jsel = 0; idx = tid; }
    else if (tid < cnt0 + cnt1) { jsel = 1; idx = tid - cnt0; }
    else                        { jsel = 2; idx = tid - cnt0 - cnt1; }
    int c = gN0 + (((jsel - m) % 3) + 3) % 3 + 3 * idx;   // global col
    int cl = c - gN0;
    int h = c / 384;
    int d = (c - h * 384) / 3;                            // rem%3==jsel
    float bias_c = __ldg(bias + c);

    const int b = gM0 >> 12;
    const int n0 = gM0 & (SEQ - 1);
    size_t base = (((size_t)(b * NHEADS + h)) * SEQ + n0) * HD + d;

    __half* p = (jsel == 0) ? (g_Qp + base)
              : (jsel == 1) ? (g_Kp + base) : (g_Vf + base);
#pragma unroll 4
    for (int r = 0; r < 128; r++)
        p[(size_t)r * HD] = __float2half(sE[r * E_STR + cl] + bias_c);
}

// ---------------------------------------------------------------------------
// Kernel 2: RMSNorm + RoPE, warp-per-row, fp16 in / fp16 out.
// Q pre-scaled by (1/sqrt(HD))*log2(e).
// ---------------------------------------------------------------------------
__global__ __launch_bounds__(256) void norm_rope_kernel(
    const float* __restrict__ rot, const float* __restrict__ qw,
    const float* __restrict__ kw)
{
    const int lane = threadIdx.x & 31;
    const int row = blockIdx.x * 8 + (threadIdx.x >> 5);
    const int n = row & (SEQ - 1);
    const size_t base = (size_t)row * HD + lane * 4;

    __half2 qh2[2], kh2[2];
    *(uint2*)qh2 = *(const uint2*)(g_Qp + base);
    *(uint2*)kh2 = *(const uint2*)(g_Kp + base);
    float2 qa = __half22float2(qh2[0]), qb = __half22float2(qh2[1]);
    float2 ka = __half22float2(kh2[0]), kb = __half22float2(kh2[1]);
    float q0v = qa.x, q1v = qa.y, q2v = qb.x, q3v = qb.y;
    float k0v = ka.x, k1v = ka.y, k2v = kb.x, k3v = kb.y;

    float q2 = q0v*q0v + q1v*q1v + q2v*q2v + q3v*q3v;
    float k2 = k0v*k0v + k1v*k1v + k2v*k2v + k3v*k3v;
#pragma unroll
    for (int off = 16; off; off >>= 1) {
        q2 += __shfl_xor_sync(0xffffffffu, q2, off);
        k2 += __shfl_xor_sync(0xffffffffu, k2, off);
    }
    float qs = rsqrtf(q2 * (1.0f / HD) + 1e-6f);
    float ks = rsqrtf(k2 * (1.0f / HD) + 1e-6f);

    float4 qwv = *(const float4*)(qw + lane * 4);
    float4 kwv = *(const float4*)(kw + lane * 4);

    float qn0 = q0v * qs * qwv.x, qn1 = q1v * qs * qwv.y;
    float qn2 = q2v * qs * qwv.z, qn3 = q3v * qs * qwv.w;
    float kn0 = k0v * ks * kwv.x, kn1 = k1v * ks * kwv.y;
    float kn2 = k2v * ks * kwv.z, kn3 = k3v * ks * kwv.w;

    const float* rp = rot + (size_t)n * 256 + lane * 8;
    float4 rA = *(const float4*)rp;
    float4 rB = *(const float4*)(rp + 4);

    const float scale = 0.08838834764831845f * 1.4426950408889634f;
    float qo0 = (rA.x * qn0 + rA.y * qn1) * scale;
    float qo1 = (rA.z * qn0 + rA.w * qn1) * scale;
    float qo2 = (rB.x * qn2 + rB.y * qn3) * scale;
    float qo3 = (rB.z * qn2 + rB.w * qn3) * scale;
    float ko0 = rA.x * kn0 + rA.y * kn1;
    float ko1 = rA.z * kn0 + rA.w * kn1;
    float ko2 = rB.x * kn2 + rB.y * kn3;
    float ko3 = rB.z * kn2 + rB.w * kn3;

    uint2 qo = make_uint2(pack_f16(qo0, qo1), pack_f16(qo2, qo3));
    uint2 ko = make_uint2(pack_f16(ko0, ko1), pack_f16(ko2, ko3));
    *(uint2*)(g_Qf + base) = qo;
    *(uint2*)(g_Kf + base) = ko;
}

// ---------------------------------------------------------------------------
// Kernel 3: Flash attention, fp16 single-term. BM=128 (8 warps), D=128.
// 128-key stages (3-stage pipeline), single BN=128 S pass per stage.
// Q fragments register-resident. No-max exp2 softmax, deferred l reduction.
// ---------------------------------------------------------------------------
#define A_STR    272                 // smem row stride bytes (128 fp16 + pad)
#define A_KARR   (128*A_STR)         // 34816 (128-row K or V array)
#define A_STAGE  (2*A_KARR)          // K(128) + V(128) = 69632
#define ATT_SMEM (3*A_STAGE)         // 208896

__global__ __launch_bounds__(256, 1) void attn_mma_kernel(float* __restrict__ out)
{
    extern __shared__ char smem[];
    const unsigned sbase = smem_u32(smem);
    const int bh = blockIdx.y;
    const int q0 = blockIdx.x << 7;          // 128 rows per CTA
    const int tid = threadIdx.x;
    const int wid = tid >> 5, lane = tid & 31;
    const int l15 = lane & 15;
    const int gr = lane >> 2, qc = (lane & 3) * 2;

    // --- Load Q tile (128 rows fp16) into stage-0 region ---
    {
        const uint4* Qf4 = (const uint4*)g_Qf;
#pragma unroll
        for (int l = 0; l < 8; l++) {
            int t = tid + (l << 8);            // 0..2047
            int row = t >> 4, c = t & 15;
            size_t gi = (((size_t)bh * SEQ + q0 + row) * HD >> 3) + c;
            cp16(sbase + row * A_STR + c * 16, Qf4 + gi);
        }
    }
    CP_COMMIT();
    CP_WAIT(0);
    __syncthreads();

    // --- Hoist Q fragments to registers (once) ---
    unsigned qf[8][4];
    {
        int arow = wid * 16 + l15;
#pragma unroll
        for (int ks = 0; ks < 8; ks++) {
            int acol = ks * 16 + (lane >> 4) * 8;
            ldsm_x4(qf[ks], sbase + arow * A_STR + acol * 2);
        }
    }
    __syncthreads();   // staging free before K/V pipeline reuses it

    const uint4* Kf4 = (const uint4*)g_Kf;
    const uint4* Vf4 = (const uint4*)g_Vf;

    // stage = 128 keys: K rows 0..127 then V rows 0..127
    auto stage_load = [&](int st, int kt) {
        unsigned sb = sbase + st * A_STAGE;
#pragma unroll
        for (int l = 0; l < 16; l++) {
            int t = tid + (l << 8);            // 0..4095
            int arr = t >> 11;                 // 0: K, 1: V
            int w = t & 2047;
            int row = w >> 4, c = w & 15;      // row 0..127
            size_t gi = (((size_t)bh * SEQ + kt * 128 + row) * HD >> 3) + c;
            const uint4* s = arr ? Vf4 : Kf4;
            cp16(sb + arr * A_KARR + row * A_STR + c * 16, s + gi);
        }
    };

    float O[16][4];
#pragma unroll
    for (int n = 0; n < 16; n++)
#pragma unroll
        for (int e = 0; e < 4; e++) O[n][e] = 0.f;
    float l0 = 0.f, l1 = 0.f;

    const int NKT = SEQ / 128;   // 32
    stage_load(0, 0); CP_COMMIT();
    stage_load(1, 1); CP_COMMIT();

    int buf = 0;
    for (int kt = 0; kt < NKT; kt++) {
        CP_WAIT(1);
        __syncthreads();        // stage kt visible; all warps done with kt-1

        // Early prefetch into the buffer freed at kt-1.
        {
            int nb = buf + 2; if (nb >= 3) nb -= 3;
            if (kt + 2 < NKT) stage_load(nb, kt + 2);
            CP_COMMIT();
        }

        unsigned sKf = sbase + buf * A_STAGE;
        unsigned sVf = sKf + A_KARR;

        // --- S = Q K^T over all 128 keys ---
        float S[16][4];
#pragma unroll
        for (int j = 0; j < 16; j++)
#pragma unroll
            for (int e = 0; e < 4; e++) S[j][e] = 0.f;

        {
            int brow_off = (lane >> 4) * 8 + (lane & 7);
            int g_kh = ((lane >> 3) & 1) * 8;
#pragma unroll
            for (int ks = 0; ks < 8; ks++) {
                int bcol = ks * 16 + g_kh;
#pragma unroll
                for (int jj = 0; jj < 8; jj++) {
                    unsigned k4[4];
                    unsigned boff = (jj * 16 + brow_off) * A_STR + bcol * 2;
                    ldsm_x4(k4, sKf + boff);
                    mma16816(S[2*jj],   qf[ks], k4);
                    mma16816(S[2*jj+1], qf[ks], k4 + 2);
                }
            }
        }

        // --- No-max softmax: P = exp2(S); accumulate partial l ---
#pragma unroll
        for (int j = 0; j < 16; j++) {
            S[j][0] = ex2(S[j][0]);
            S[j][1] = ex2(S[j][1]);
            S[j][2] = ex2(S[j][2]);
            S[j][3] = ex2(S[j][3]);
            l0 += S[j][0] + S[j][1];
            l1 += S[j][2] + S[j][3];
        }

        // --- O += P V over all 128 keys ---
        {
            int vrow_off = (((lane >> 3) & 1) * 8) + (lane & 7);
            int vcol_off = (lane >> 4) * 16;
#pragma unroll
            for (int t = 0; t < 8; t++) {
                unsigned ph[4];
                const float* s0 = S[2 * t];
                const float* s1 = S[2 * t + 1];
                ph[0] = pack_f16(s0[0], s0[1]);
                ph[1] = pack_f16(s0[2], s0[3]);
                ph[2] = pack_f16(s1[0], s1[1]);
                ph[3] = pack_f16(s1[2], s1[3]);
#pragma unroll
                for (int nn = 0; nn < 8; nn += 2) {
                    unsigned vha[4], vhb[4];
                    unsigned va = (t * 16 + vrow_off) * A_STR
                                  + nn * 32 + vcol_off;
                    ldsm_x4_t(vha, sVf + va);
                    ldsm_x4_t(vhb, sVf + va + 32);
                    mma16816(O[2*nn],   ph, vha);
                    mma16816(O[2*nn+1], ph, vha + 2);
                    mma16816(O[2*nn+2], ph, vhb);
                    mma16816(O[2*nn+3], ph, vhb + 2);
                }
            }
        }

        if (++buf == 3) buf = 0;
    }

    // --- Final l reduction across the 4 lanes of each row group ---
    l0 += __shfl_xor_sync(0xffffffffu, l0, 1);
    l0 += __shfl_xor_sync(0xffffffffu, l0, 2);
    l1 += __shfl_xor_sync(0xffffffffu, l1, 1);
    l1 += __shfl_xor_sync(0xffffffffu, l1, 2);

    // --- Write output ---
    const int b = bh >> 4, h = bh & 15;
    float inv0 = __fdividef(1.0f, l0);
    float inv1 = __fdividef(1.0f, l1);
    int n0g = q0 + wid * 16 + gr;
    float* o0 = out + ((size_t)b * SEQ + n0g) * DIM + h * HD;
    float* o1 = out + ((size_t)b * SEQ + n0g + 8) * DIM + h * HD;
#pragma unroll
    for (int n = 0; n < 16; n++) {
        int d = n * 8 + qc;
        float2 w0 = make_float2(O[n][0] * inv0, O[n][1] * inv0);
        float2 w1 = make_float2(O[n][2] * inv1, O[n][3] * inv1);
        *(float2*)(o0 + d) = w0;
        *(float2*)(o1 + d) = w1;
    }
}

// ---------------------------------------------------------------------------
extern "C" void kernel_launch(void* const* d_in, const int* in_sizes, int n_in,
                              void* d_out, int out_size)
{
    const float* x    = (const float*)d_in[0];
    const float* rot  = (const float*)d_in[1];
    const float* W    = (const float*)d_in[2];
    const float* bias = (const float*)d_in[3];
    const float* qw   = (const float*)d_in[4];
    const float* kw   = (const float*)d_in[5];
    float* out = (float*)d_out;

    convert_x_kernel<<<(MROWS * DIM) / (256 * 8), 256>>>(x);
    convert_w_kernel<<<dim3(QKV_COLS / 32, DIM / 32), dim3(32, 8)>>>(W);

    cudaFuncSetAttribute(qkv_gemm_mma_kernel,
                         cudaFuncAttributeMaxDynamicSharedMemorySize, GEMM_SMEM);
    qkv_gemm_mma_kernel<<<dim3(QKV_COLS / 256, MROWS / 128), 256, GEMM_SMEM>>>(bias);

    norm_rope_kernel<<<(BATCH * NHEADS * SEQ) / 8, 256>>>(rot, qw, kw);

    cudaFuncSetAttribute(attn_mma_kernel,
                         cudaFuncAttributeMaxDynamicSharedMemorySize, ATT_SMEM);
    attn_mma_kernel<<<dim3(SEQ / 128, BATCH * NHEADS), 256, ATT_SMEM>>>(out);
}